// round 9
// baseline (speedup 1.0000x reference)
#include <cuda_runtime.h>
#include <cuda_fp16.h>
#include <cstdint>

// Problem constants
#define B_   1024
#define P_   24
#define H_   2048
#define K1_  4096   // H*R
#define N1_  2048   // H
#define K2_  2048
#define N2_  1024   // H/2
#define OUTP 4

// Scratch (allocation-free rule: __device__ globals)
__device__ __half g_xh [(size_t)B_ * P_ * H_];    // x   -> fp16
__device__ __half g_w1h[(size_t)P_ * K1_ * N1_];  // W1  -> fp16
__device__ __half g_w2h[(size_t)P_ * K2_ * N2_];  // W2  -> fp16
__device__ __half g_h1h[(size_t)P_ * B_ * N1_];   // layer1 out fp16
__device__ float  g_h2 [(size_t)P_ * B_ * N2_];   // layer2 out fp32

// ---------------------------------------------------------------------------
// helpers
// ---------------------------------------------------------------------------
__device__ __forceinline__ void mma_f16_f32(float* c, const uint32_t* a, const uint32_t* b) {
    asm volatile(
        "mma.sync.aligned.m16n8k16.row.col.f32.f16.f16.f32 "
        "{%0,%1,%2,%3}, {%4,%5,%6,%7}, {%8,%9}, {%0,%1,%2,%3};"
        : "+f"(c[0]), "+f"(c[1]), "+f"(c[2]), "+f"(c[3])
        : "r"(a[0]), "r"(a[1]), "r"(a[2]), "r"(a[3]), "r"(b[0]), "r"(b[1]));
}

__device__ __forceinline__ void ldsm4(uint32_t addr, uint32_t* r) {
    asm volatile("ldmatrix.sync.aligned.m8n8.x4.shared.b16 {%0,%1,%2,%3}, [%4];"
                 : "=r"(r[0]), "=r"(r[1]), "=r"(r[2]), "=r"(r[3]) : "r"(addr));
}
__device__ __forceinline__ void ldsm4t(uint32_t addr, uint32_t* r) {
    asm volatile("ldmatrix.sync.aligned.m8n8.x4.trans.shared.b16 {%0,%1,%2,%3}, [%4];"
                 : "=r"(r[0]), "=r"(r[1]), "=r"(r[2]), "=r"(r[3]) : "r"(addr));
}

__device__ __forceinline__ void cp_async16(uint32_t smem_addr, const void* gptr, int src_size) {
    asm volatile("cp.async.cg.shared.global [%0], [%1], 16, %2;"
                 :: "r"(smem_addr), "l"(gptr), "r"(src_size));
}
__device__ __forceinline__ void cp_commit() {
    asm volatile("cp.async.commit_group;" ::: "memory");
}
template <int N>
__device__ __forceinline__ void cp_wait() {
    asm volatile("cp.async.wait_group %0;" :: "n"(N) : "memory");
}

__device__ __forceinline__ float gelu_exact(float v) {
    return 0.5f * v * (1.0f + erff(v * 0.7071067811865476f));
}

// ---------------------------------------------------------------------------
// Prepass: fp32 -> fp16 (RN) streaming convert
// ---------------------------------------------------------------------------
__global__ void cvt_kernel(const float* __restrict__ in, __half* __restrict__ outp, size_t n4) {
    size_t i = (size_t)blockIdx.x * blockDim.x + threadIdx.x;
    size_t stride = (size_t)gridDim.x * blockDim.x;
    for (; i < n4; i += stride) {
        float4 v = ((const float4*)in)[i];
        ((__half2*)outp)[2 * i]     = __floats2half2_rn(v.x, v.y);
        ((__half2*)outp)[2 * i + 1] = __floats2half2_rn(v.z, v.w);
    }
}

// ---------------------------------------------------------------------------
// fp16 grouped GEMM + GELU.  CTA tile 128(m) x 128(n), BK=64, 3-stage cp.async.
// 128 threads = 4 warps (2M x 2N), warp tile 64x64, fragment double-buffering.
// TWO CTAs per SM (107.5 KB smem each, 215 KB total; 128 thr -> 256 reg budget).
// MODE 0: A = windowed g_xh[B,P,H] (K=4096, out g_h1h fp16)
// MODE 1: A = g_h1h [p][b][k]      (K=2048, out g_h2  fp32)
// ---------------------------------------------------------------------------
#define BM 128
#define BN 128
#define BK 64
#define ASTRH 72              // A row stride (halves): 144B, LDSM conflict-free
#define BSTRH 136             // B row stride (halves): 272B, LDSM conflict-free
#define ASZB (BM * ASTRH * 2)          // 18432 B
#define BSZB (BK * BSTRH * 2)          // 17408 B
#define STGB (ASZB + BSZB)             // 35840 B / stage
#define NSTG 3
#define SMEM_BYTES (NSTG * STGB)       // 107520

template <int MODE>
__global__ void __launch_bounds__(128, 2)
gemm_f16_kernel(const __half* __restrict__ A, const __half* __restrict__ W,
                const float* __restrict__ bias, void* __restrict__ Cout,
                int K, int N) {
    extern __shared__ __half smem[];
    const uint32_t smem_u = (uint32_t)__cvta_generic_to_shared(smem);

    const int p    = blockIdx.z;
    const int bm   = blockIdx.y;
    const int bn   = blockIdx.x;
    const int tid  = threadIdx.x;
    const int wid  = tid >> 5;
    const int lane = tid & 31;
    const int warpM = wid >> 1;    // 0..1  (64 rows)
    const int warpN = wid & 1;     // 0..1  (64 cols)
    const int g  = lane >> 2;      // 0..7
    const int cc = lane & 3;       // 0..3

    // ldmatrix lane address components
    const int l7 = lane & 7;
    const int lb = (lane >> 3) & 1;
    const int lk = lane >> 4;
    const uint32_t aoff = ((warpM * 64 + lb * 8 + l7) * ASTRH + lk * 8) * 2;
    const uint32_t boff = ASZB + ((lb * 8 + l7) * BSTRH + warpN * 64 + lk * 8) * 2;

    float acc[4][8][4];
#pragma unroll
    for (int mf = 0; mf < 4; mf++)
#pragma unroll
        for (int nf = 0; nf < 8; nf++)
#pragma unroll
            for (int i = 0; i < 4; i++) acc[mf][nf][i] = 0.f;

    const __half* Wp = W + (size_t)p * K * N + (size_t)bn * BN;

    auto load_tiles = [&](int kt, int buf) {
        uint32_t sbase = smem_u + buf * STGB;
        // A: 128 rows x 64 halves = 1024 x 16B chunks -> 8 per thread
#pragma unroll
        for (int i = 0; i < 8; i++) {
            int c  = tid + i * 128;
            int m  = c >> 3;
            int kl = (c & 7) * 8;
            int kg = kt * BK + kl;
            const __half* ga;
            int sz = 16;
            if (MODE == 0) {
                int half_ = (kg >= H_) ? 1 : 0;
                int pp    = p + half_;
                int kk    = kg - half_ * H_;
                if (pp >= P_) { pp = P_ - 1; sz = 0; }   // right-edge zero pad
                ga = A + ((size_t)(bm * BM + m) * P_ + pp) * H_ + kk;
            } else {
                ga = A + ((size_t)p * B_ + bm * BM + m) * (size_t)K + kg;
            }
            cp_async16(sbase + (m * ASTRH + kl) * 2, ga, sz);
        }
        // B: 64 rows x 128 halves = 1024 x 16B chunks -> 8 per thread
#pragma unroll
        for (int i = 0; i < 8; i++) {
            int c  = tid + i * 128;
            int kb = c >> 4;              // 0..63
            int nb = (c & 15) * 8;        // 0..120
            const __half* gb = Wp + (size_t)(kt * BK + kb) * N + nb;
            cp_async16(sbase + ASZB + (kb * BSTRH + nb) * 2, gb, 16);
        }
    };

    const int NKT = K / BK;
    load_tiles(0, 0); cp_commit();
    load_tiles(1, 1); cp_commit();

    uint32_t a[2][4][4], b[2][4][4];

    for (int kt = 0; kt < NKT; ++kt) {
        cp_wait<1>();
        __syncthreads();
        if (kt + 2 < NKT) load_tiles(kt + 2, (kt + 2) % NSTG);
        cp_commit();                  // possibly-empty group keeps invariant

        const uint32_t sbase = smem_u + (kt % NSTG) * STGB;
        const uint32_t aB = sbase + aoff;
        const uint32_t bB = sbase + boff;

        // prefetch ks=0 fragments
#pragma unroll
        for (int f = 0; f < 4; f++) ldsm4(aB + f * (16 * ASTRH * 2), a[0][f]);
#pragma unroll
        for (int nf = 0; nf < 4; nf++) ldsm4t(bB + nf * 32, b[0][nf]);

#pragma unroll
        for (int ks = 0; ks < 4; ks++) {
            const int cb = ks & 1;
            if (ks < 3) {
                const int nb2 = cb ^ 1;
                const uint32_t akk = aB + (ks + 1) * 32;
                const uint32_t bkk = bB + (ks + 1) * (16 * BSTRH * 2);
#pragma unroll
                for (int f = 0; f < 4; f++) ldsm4(akk + f * (16 * ASTRH * 2), a[nb2][f]);
#pragma unroll
                for (int nf = 0; nf < 4; nf++) ldsm4t(bkk + nf * 32, b[nb2][nf]);
            }
#pragma unroll
            for (int mf = 0; mf < 4; mf++)
#pragma unroll
                for (int nf = 0; nf < 4; nf++) {
                    mma_f16_f32(acc[mf][2 * nf],     a[cb][mf], &b[cb][nf][0]);
                    mma_f16_f32(acc[mf][2 * nf + 1], a[cb][mf], &b[cb][nf][2]);
                }
        }
    }

    // Epilogue: bias + exact GELU.  MODE0 -> fp16 h1, MODE1 -> fp32 h2.
    const float* brow = bias + (size_t)p * N;
#pragma unroll
    for (int mf = 0; mf < 4; mf++) {
        int row0 = bm * BM + warpM * 64 + mf * 16 + g;
        size_t base0 = ((size_t)p * B_ + row0) * (size_t)N;
        size_t base8 = base0 + (size_t)8 * N;
#pragma unroll
        for (int nf = 0; nf < 8; nf++) {
            int n = bn * BN + warpN * 64 + nf * 8 + cc * 2;
            float bv0 = __ldg(brow + n);
            float bv1 = __ldg(brow + n + 1);
            float v0 = gelu_exact(acc[mf][nf][0] + bv0);
            float v1 = gelu_exact(acc[mf][nf][1] + bv1);
            float v2 = gelu_exact(acc[mf][nf][2] + bv0);
            float v3 = gelu_exact(acc[mf][nf][3] + bv1);
            if (MODE == 0) {
                __half* C = (__half*)Cout;
                *(__half2*)(C + base0 + n) = __floats2half2_rn(v0, v1);
                *(__half2*)(C + base8 + n) = __floats2half2_rn(v2, v3);
            } else {
                float* C = (float*)Cout;
                *(float2*)(C + base0 + n) = make_float2(v0, v1);
                *(float2*)(C + base8 + n) = make_float2(v2, v3);
            }
        }
    }
}

// ---------------------------------------------------------------------------
// Layer 3: out[b, p*4+o] = relu(sum_k h2[p][b][k] * W3[p][k][o] + b3[p][o])
// ---------------------------------------------------------------------------
__global__ void l3_kernel(const float* __restrict__ h2, const float* __restrict__ W3,
                          const float* __restrict__ b3, float* __restrict__ out) {
    int p = blockIdx.x, b = blockIdx.y;
    int tid = threadIdx.x;
    const float* hrow = h2 + ((size_t)p * B_ + b) * N2_;
    const float* w    = W3 + (size_t)p * N2_ * OUTP;

    float a0 = 0.f, a1 = 0.f, a2 = 0.f, a3 = 0.f;
    for (int k = tid; k < N2_; k += 128) {
        float hv = hrow[k];
        const float* wr = w + k * OUTP;
        a0 += hv * wr[0]; a1 += hv * wr[1]; a2 += hv * wr[2]; a3 += hv * wr[3];
    }
#pragma unroll
    for (int off = 16; off; off >>= 1) {
        a0 += __shfl_down_sync(0xffffffffu, a0, off);
        a1 += __shfl_down_sync(0xffffffffu, a1, off);
        a2 += __shfl_down_sync(0xffffffffu, a2, off);
        a3 += __shfl_down_sync(0xffffffffu, a3, off);
    }
    __shared__ float sred[4][4];
    int warp = tid >> 5, lane = tid & 31;
    if (lane == 0) {
        sred[warp][0] = a0; sred[warp][1] = a1; sred[warp][2] = a2; sred[warp][3] = a3;
    }
    __syncthreads();
    if (tid < 4) {
        float s = sred[0][tid] + sred[1][tid] + sred[2][tid] + sred[3][tid]
                + b3[p * OUTP + tid];
        out[(size_t)b * (P_ * OUTP) + p * OUTP + tid] = fmaxf(s, 0.f);
    }
}

// ---------------------------------------------------------------------------
extern "C" void kernel_launch(void* const* d_in, const int* in_sizes, int n_in,
                              void* d_out, int out_size) {
    const float* x  = (const float*)d_in[0];
    const float* W1 = (const float*)d_in[1];
    const float* b1 = (const float*)d_in[2];
    const float* W2 = (const float*)d_in[3];
    const float* b2 = (const float*)d_in[4];
    const float* W3 = (const float*)d_in[5];
    const float* b3 = (const float*)d_in[6];
    float* out = (float*)d_out;

    __half *xh, *w1h, *w2h, *h1h;
    float *h2;
    cudaGetSymbolAddress((void**)&xh,  g_xh);
    cudaGetSymbolAddress((void**)&w1h, g_w1h);
    cudaGetSymbolAddress((void**)&w2h, g_w2h);
    cudaGetSymbolAddress((void**)&h1h, g_h1h);
    cudaGetSymbolAddress((void**)&h2,  g_h2);

    cudaFuncSetAttribute((const void*)gemm_f16_kernel<0>,
                         cudaFuncAttributeMaxDynamicSharedMemorySize, SMEM_BYTES);
    cudaFuncSetAttribute((const void*)gemm_f16_kernel<1>,
                         cudaFuncAttributeMaxDynamicSharedMemorySize, SMEM_BYTES);

    // Prepass: fp32 -> fp16 converts (x, W1, W2)
    cvt_kernel<<<2048, 256>>>(x,  xh,  (size_t)B_ * P_ * H_ / 4);
    cvt_kernel<<<8192, 256>>>(W1, w1h, (size_t)P_ * K1_ * N1_ / 4);
    cvt_kernel<<<4096, 256>>>(W2, w2h, (size_t)P_ * K2_ * N2_ / 4);

    // Layer 1: [1024, 4096] @ [4096, 2048] per p, GELU -> fp16 h1
    gemm_f16_kernel<0><<<dim3(N1_ / BN, B_ / BM, P_), 128, SMEM_BYTES>>>(
        xh, w1h, b1, h1h, K1_, N1_);
    // Layer 2: [1024, 2048] @ [2048, 1024] per p, GELU -> fp32 h2
    gemm_f16_kernel<1><<<dim3(N2_ / BN, B_ / BM, P_), 128, SMEM_BYTES>>>(
        h1h, w2h, b2, h2, K2_, N2_);
    // Layer 3: tiny N=4 + ReLU
    l3_kernel<<<dim3(P_, B_), 128>>>(h2, W3, b3, out);
}

// round 10
// speedup vs baseline: 1.1864x; 1.1864x over previous
#include <cuda_runtime.h>
#include <cuda_fp16.h>
#include <cstdint>

// Problem constants
#define B_   1024
#define P_   24
#define H_   2048
#define K1_  4096   // H*R
#define N1_  2048   // H
#define K2_  2048
#define N2_  1024   // H/2
#define OUTP 4

// Scratch (allocation-free rule: __device__ globals)
__device__ __half g_xh [(size_t)B_ * P_ * H_];    // x   -> fp16
__device__ __half g_w1h[(size_t)P_ * K1_ * N1_];  // W1  -> fp16
__device__ __half g_w2h[(size_t)P_ * K2_ * N2_];  // W2  -> fp16
__device__ __half g_h1h[(size_t)P_ * B_ * N1_];   // layer1 out fp16
__device__ float  g_h2 [(size_t)P_ * B_ * N2_];   // layer2 out fp32

// ---------------------------------------------------------------------------
// helpers
// ---------------------------------------------------------------------------
__device__ __forceinline__ void mma_f16_f32(float* c, const uint32_t* a, const uint32_t* b) {
    asm volatile(
        "mma.sync.aligned.m16n8k16.row.col.f32.f16.f16.f32 "
        "{%0,%1,%2,%3}, {%4,%5,%6,%7}, {%8,%9}, {%0,%1,%2,%3};"
        : "+f"(c[0]), "+f"(c[1]), "+f"(c[2]), "+f"(c[3])
        : "r"(a[0]), "r"(a[1]), "r"(a[2]), "r"(a[3]), "r"(b[0]), "r"(b[1]));
}

__device__ __forceinline__ void ldsm4(uint32_t addr, uint32_t* r) {
    asm volatile("ldmatrix.sync.aligned.m8n8.x4.shared.b16 {%0,%1,%2,%3}, [%4];"
                 : "=r"(r[0]), "=r"(r[1]), "=r"(r[2]), "=r"(r[3]) : "r"(addr));
}
__device__ __forceinline__ void ldsm4t(uint32_t addr, uint32_t* r) {
    asm volatile("ldmatrix.sync.aligned.m8n8.x4.trans.shared.b16 {%0,%1,%2,%3}, [%4];"
                 : "=r"(r[0]), "=r"(r[1]), "=r"(r[2]), "=r"(r[3]) : "r"(addr));
}

__device__ __forceinline__ void cp_async16(uint32_t smem_addr, const void* gptr, int src_size) {
    asm volatile("cp.async.cg.shared.global [%0], [%1], 16, %2;"
                 :: "r"(smem_addr), "l"(gptr), "r"(src_size));
}
__device__ __forceinline__ void cp_commit() {
    asm volatile("cp.async.commit_group;" ::: "memory");
}
template <int N>
__device__ __forceinline__ void cp_wait() {
    asm volatile("cp.async.wait_group %0;" :: "n"(N) : "memory");
}

__device__ __forceinline__ float gelu_exact(float v) {
    return 0.5f * v * (1.0f + erff(v * 0.7071067811865476f));
}

// ---------------------------------------------------------------------------
// Prepass: fp32 -> fp16 (RN) streaming convert
// ---------------------------------------------------------------------------
__global__ void cvt_kernel(const float* __restrict__ in, __half* __restrict__ outp, size_t n4) {
    size_t i = (size_t)blockIdx.x * blockDim.x + threadIdx.x;
    size_t stride = (size_t)gridDim.x * blockDim.x;
    for (; i < n4; i += stride) {
        float4 v = ((const float4*)in)[i];
        ((__half2*)outp)[2 * i]     = __floats2half2_rn(v.x, v.y);
        ((__half2*)outp)[2 * i + 1] = __floats2half2_rn(v.z, v.w);
    }
}

// ---------------------------------------------------------------------------
// fp16 grouped GEMM + GELU.  CTA tile 128x128, BK=64, 3-stage cp.async.
// 128 threads = 4 warps (2M x 2N), warp tile 64x64.
// Restructured pipeline: deep wait + barrier publishes stage kt AND kt+1;
// next-kt ks0 fragments prefetched right after the barrier and hidden under
// ks3's MMA block; global loads issued after the barrier (WAR-safe).
// TWO CTAs per SM.
// MODE 0: A = windowed g_xh[B,P,H] (K=4096, out g_h1h fp16)
// MODE 1: A = g_h1h [p][b][k]      (K=2048, out g_h2  fp32)
// ---------------------------------------------------------------------------
#define BM 128
#define BN 128
#define BK 64
#define ASTRH 72              // A row stride (halves): 144B, LDSM conflict-free
#define BSTRH 136             // B row stride (halves): 272B, LDSM conflict-free
#define ASZB (BM * ASTRH * 2)          // 18432 B
#define BSZB (BK * BSTRH * 2)          // 17408 B
#define STGB (ASZB + BSZB)             // 35840 B / stage
#define NSTG 3
#define SMEM_BYTES (NSTG * STGB)       // 107520

template <int MODE>
__global__ void __launch_bounds__(128, 2)
gemm_f16_kernel(const __half* __restrict__ A, const __half* __restrict__ W,
                const float* __restrict__ bias, void* __restrict__ Cout,
                int K, int N) {
    extern __shared__ __half smem[];
    const uint32_t smem_u = (uint32_t)__cvta_generic_to_shared(smem);

    const int p    = blockIdx.z;
    const int bm   = blockIdx.y;
    const int bn   = blockIdx.x;
    const int tid  = threadIdx.x;
    const int wid  = tid >> 5;
    const int lane = tid & 31;
    const int warpM = wid >> 1;    // 0..1  (64 rows)
    const int warpN = wid & 1;     // 0..1  (64 cols)
    const int g  = lane >> 2;      // 0..7
    const int cc = lane & 3;       // 0..3

    // ldmatrix lane address components
    const int l7 = lane & 7;
    const int lb = (lane >> 3) & 1;
    const int lk = lane >> 4;
    const uint32_t aoff = ((warpM * 64 + lb * 8 + l7) * ASTRH + lk * 8) * 2;
    const uint32_t boff = ASZB + ((lb * 8 + l7) * BSTRH + warpN * 64 + lk * 8) * 2;

    float acc[4][8][4];
#pragma unroll
    for (int mf = 0; mf < 4; mf++)
#pragma unroll
        for (int nf = 0; nf < 8; nf++)
#pragma unroll
            for (int i = 0; i < 4; i++) acc[mf][nf][i] = 0.f;

    const __half* Wp = W + (size_t)p * K * N + (size_t)bn * BN;

    auto load_tiles = [&](int kt, int buf) {
        uint32_t sbase = smem_u + buf * STGB;
        // A: 128 rows x 64 halves = 1024 x 16B chunks -> 8 per thread
#pragma unroll
        for (int i = 0; i < 8; i++) {
            int c  = tid + i * 128;
            int m  = c >> 3;
            int kl = (c & 7) * 8;
            int kg = kt * BK + kl;
            const __half* ga;
            int sz = 16;
            if (MODE == 0) {
                int half_ = (kg >= H_) ? 1 : 0;
                int pp    = p + half_;
                int kk    = kg - half_ * H_;
                if (pp >= P_) { pp = P_ - 1; sz = 0; }   // right-edge zero pad
                ga = A + ((size_t)(bm * BM + m) * P_ + pp) * H_ + kk;
            } else {
                ga = A + ((size_t)p * B_ + bm * BM + m) * (size_t)K + kg;
            }
            cp_async16(sbase + (m * ASTRH + kl) * 2, ga, sz);
        }
        // B: 64 rows x 128 halves = 1024 x 16B chunks -> 8 per thread
#pragma unroll
        for (int i = 0; i < 8; i++) {
            int c  = tid + i * 128;
            int kb = c >> 4;              // 0..63
            int nb = (c & 15) * 8;        // 0..120
            const __half* gb = Wp + (size_t)(kt * BK + kb) * N + nb;
            cp_async16(sbase + ASZB + (kb * BSTRH + nb) * 2, gb, 16);
        }
    };

    uint32_t a[2][4][4], b[2][4][4];

    auto prefetch = [&](uint32_t sbase, int ks, int buf) {
        const uint32_t akk = sbase + aoff + ks * 32;             // +16 halves along k
        const uint32_t bkk = sbase + boff + ks * (16 * BSTRH * 2);
#pragma unroll
        for (int f = 0; f < 4; f++) ldsm4(akk + f * (16 * ASTRH * 2), a[buf][f]);
#pragma unroll
        for (int nf = 0; nf < 4; nf++) ldsm4t(bkk + nf * 32, b[buf][nf]);
    };
    auto mma_block = [&](int buf) {
#pragma unroll
        for (int mf = 0; mf < 4; mf++)
#pragma unroll
            for (int nf = 0; nf < 4; nf++) {
                mma_f16_f32(acc[mf][2 * nf],     a[buf][mf], &b[buf][nf][0]);
                mma_f16_f32(acc[mf][2 * nf + 1], a[buf][mf], &b[buf][nf][2]);
            }
    };

    const int NKT = K / BK;   // >= 16
    load_tiles(0, 0); cp_commit();
    load_tiles(1, 1); cp_commit();
    cp_wait<1>();             // stage 0 complete
    __syncthreads();          // stage 0 published
    prefetch(smem_u, 0, 0);   // frags(kt=0, ks=0) -> buf0

    for (int kt = 0; kt < NKT; ++kt) {
        const uint32_t sbase = smem_u + (kt % NSTG) * STGB;

        // ks0..ks2: intra-kt fragment double buffering (ks -> buf[ks&1])
#pragma unroll
        for (int ks = 0; ks < 3; ks++) {
            prefetch(sbase, ks + 1, (ks + 1) & 1);
            mma_block(ks & 1);
        }

        // Publish stage kt+1 CTA-wide; all smem reads of stage kt already issued.
        cp_wait<0>();
        __syncthreads();

        // Post-barrier: prefetch next kt's ks0 (hidden under ks3's MMAs below),
        // and issue global loads for stage kt+2 (WAR-safe: stage (kt+2)%3 was
        // last read before the PREVIOUS barrier).
        if (kt + 1 < NKT) prefetch(smem_u + ((kt + 1) % NSTG) * STGB, 0, 0);
        if (kt + 2 < NKT) { load_tiles(kt + 2, (kt + 2) % NSTG); cp_commit(); }

        mma_block(1);   // ks3
    }

    // Epilogue: bias + exact GELU.  MODE0 -> fp16 h1, MODE1 -> fp32 h2.
    const float* brow = bias + (size_t)p * N;
#pragma unroll
    for (int mf = 0; mf < 4; mf++) {
        int row0 = bm * BM + warpM * 64 + mf * 16 + g;
        size_t base0 = ((size_t)p * B_ + row0) * (size_t)N;
        size_t base8 = base0 + (size_t)8 * N;
#pragma unroll
        for (int nf = 0; nf < 8; nf++) {
            int n = bn * BN + warpN * 64 + nf * 8 + cc * 2;
            float bv0 = __ldg(brow + n);
            float bv1 = __ldg(brow + n + 1);
            float v0 = gelu_exact(acc[mf][nf][0] + bv0);
            float v1 = gelu_exact(acc[mf][nf][1] + bv1);
            float v2 = gelu_exact(acc[mf][nf][2] + bv0);
            float v3 = gelu_exact(acc[mf][nf][3] + bv1);
            if (MODE == 0) {
                __half* C = (__half*)Cout;
                *(__half2*)(C + base0 + n) = __floats2half2_rn(v0, v1);
                *(__half2*)(C + base8 + n) = __floats2half2_rn(v2, v3);
            } else {
                float* C = (float*)Cout;
                *(float2*)(C + base0 + n) = make_float2(v0, v1);
                *(float2*)(C + base8 + n) = make_float2(v2, v3);
            }
        }
    }
}

// ---------------------------------------------------------------------------
// Layer 3: out[b, p*4+o] = relu(sum_k h2[p][b][k] * W3[p][k][o] + b3[p][o])
// ---------------------------------------------------------------------------
__global__ void l3_kernel(const float* __restrict__ h2, const float* __restrict__ W3,
                          const float* __restrict__ b3, float* __restrict__ out) {
    int p = blockIdx.x, b = blockIdx.y;
    int tid = threadIdx.x;
    const float* hrow = h2 + ((size_t)p * B_ + b) * N2_;
    const float* w    = W3 + (size_t)p * N2_ * OUTP;

    float a0 = 0.f, a1 = 0.f, a2 = 0.f, a3 = 0.f;
    for (int k = tid; k < N2_; k += 128) {
        float hv = hrow[k];
        const float* wr = w + k * OUTP;
        a0 += hv * wr[0]; a1 += hv * wr[1]; a2 += hv * wr[2]; a3 += hv * wr[3];
    }
#pragma unroll
    for (int off = 16; off; off >>= 1) {
        a0 += __shfl_down_sync(0xffffffffu, a0, off);
        a1 += __shfl_down_sync(0xffffffffu, a1, off);
        a2 += __shfl_down_sync(0xffffffffu, a2, off);
        a3 += __shfl_down_sync(0xffffffffu, a3, off);
    }
    __shared__ float sred[4][4];
    int warp = tid >> 5, lane = tid & 31;
    if (lane == 0) {
        sred[warp][0] = a0; sred[warp][1] = a1; sred[warp][2] = a2; sred[warp][3] = a3;
    }
    __syncthreads();
    if (tid < 4) {
        float s = sred[0][tid] + sred[1][tid] + sred[2][tid] + sred[3][tid]
                + b3[p * OUTP + tid];
        out[(size_t)b * (P_ * OUTP) + p * OUTP + tid] = fmaxf(s, 0.f);
    }
}

// ---------------------------------------------------------------------------
extern "C" void kernel_launch(void* const* d_in, const int* in_sizes, int n_in,
                              void* d_out, int out_size) {
    const float* x  = (const float*)d_in[0];
    const float* W1 = (const float*)d_in[1];
    const float* b1 = (const float*)d_in[2];
    const float* W2 = (const float*)d_in[3];
    const float* b2 = (const float*)d_in[4];
    const float* W3 = (const float*)d_in[5];
    const float* b3 = (const float*)d_in[6];
    float* out = (float*)d_out;

    __half *xh, *w1h, *w2h, *h1h;
    float *h2;
    cudaGetSymbolAddress((void**)&xh,  g_xh);
    cudaGetSymbolAddress((void**)&w1h, g_w1h);
    cudaGetSymbolAddress((void**)&w2h, g_w2h);
    cudaGetSymbolAddress((void**)&h1h, g_h1h);
    cudaGetSymbolAddress((void**)&h2,  g_h2);

    cudaFuncSetAttribute((const void*)gemm_f16_kernel<0>,
                         cudaFuncAttributeMaxDynamicSharedMemorySize, SMEM_BYTES);
    cudaFuncSetAttribute((const void*)gemm_f16_kernel<1>,
                         cudaFuncAttributeMaxDynamicSharedMemorySize, SMEM_BYTES);

    // Prepass: fp32 -> fp16 converts (x, W1, W2)
    cvt_kernel<<<2048, 256>>>(x,  xh,  (size_t)B_ * P_ * H_ / 4);
    cvt_kernel<<<8192, 256>>>(W1, w1h, (size_t)P_ * K1_ * N1_ / 4);
    cvt_kernel<<<4096, 256>>>(W2, w2h, (size_t)P_ * K2_ * N2_ / 4);

    // Layer 1: [1024, 4096] @ [4096, 2048] per p, GELU -> fp16 h1
    gemm_f16_kernel<0><<<dim3(N1_ / BN, B_ / BM, P_), 128, SMEM_BYTES>>>(
        xh, w1h, b1, h1h, K1_, N1_);
    // Layer 2: [1024, 2048] @ [2048, 1024] per p, GELU -> fp32 h2
    gemm_f16_kernel<1><<<dim3(N2_ / BN, B_ / BM, P_), 128, SMEM_BYTES>>>(
        h1h, w2h, b2, h2, K2_, N2_);
    // Layer 3: tiny N=4 + ReLU
    l3_kernel<<<dim3(P_, B_), 128>>>(h2, W3, b3, out);
}

// round 11
// speedup vs baseline: 1.2184x; 1.0270x over previous
#include <cuda_runtime.h>
#include <cuda_fp16.h>
#include <cstdint>

// Problem constants
#define B_   1024
#define P_   24
#define H_   2048
#define K1_  4096   // H*R
#define N1_  2048   // H
#define K2_  2048
#define N2_  1024   // H/2
#define OUTP 4

// Scratch (allocation-free rule: __device__ globals)
__device__ __half g_xh [(size_t)B_ * P_ * H_];    // x   -> fp16
__device__ __half g_w1h[(size_t)P_ * K1_ * N1_];  // W1  -> fp16
__device__ __half g_w2h[(size_t)P_ * K2_ * N2_];  // W2  -> fp16
__device__ __half g_h1h[(size_t)P_ * B_ * N1_];   // layer1 out fp16
__device__ float  g_h2 [(size_t)P_ * B_ * N2_];   // layer2 out fp32

// ---------------------------------------------------------------------------
// helpers
// ---------------------------------------------------------------------------
__device__ __forceinline__ void mma_f16_f32(float* c, const uint32_t* a, const uint32_t* b) {
    asm volatile(
        "mma.sync.aligned.m16n8k16.row.col.f32.f16.f16.f32 "
        "{%0,%1,%2,%3}, {%4,%5,%6,%7}, {%8,%9}, {%0,%1,%2,%3};"
        : "+f"(c[0]), "+f"(c[1]), "+f"(c[2]), "+f"(c[3])
        : "r"(a[0]), "r"(a[1]), "r"(a[2]), "r"(a[3]), "r"(b[0]), "r"(b[1]));
}

__device__ __forceinline__ void ldsm4(uint32_t addr, uint32_t* r) {
    asm volatile("ldmatrix.sync.aligned.m8n8.x4.shared.b16 {%0,%1,%2,%3}, [%4];"
                 : "=r"(r[0]), "=r"(r[1]), "=r"(r[2]), "=r"(r[3]) : "r"(addr));
}
__device__ __forceinline__ void ldsm4t(uint32_t addr, uint32_t* r) {
    asm volatile("ldmatrix.sync.aligned.m8n8.x4.trans.shared.b16 {%0,%1,%2,%3}, [%4];"
                 : "=r"(r[0]), "=r"(r[1]), "=r"(r[2]), "=r"(r[3]) : "r"(addr));
}

__device__ __forceinline__ void cp_async16(uint32_t smem_addr, const void* gptr, int src_size) {
    asm volatile("cp.async.cg.shared.global [%0], [%1], 16, %2;"
                 :: "r"(smem_addr), "l"(gptr), "r"(src_size));
}
__device__ __forceinline__ void cp_commit() {
    asm volatile("cp.async.commit_group;" ::: "memory");
}
template <int N>
__device__ __forceinline__ void cp_wait() {
    asm volatile("cp.async.wait_group %0;" :: "n"(N) : "memory");
}

__device__ __forceinline__ float gelu_exact(float v) {
    return 0.5f * v * (1.0f + erff(v * 0.7071067811865476f));
}

// ---------------------------------------------------------------------------
// Prepass: fp32 -> fp16 (RN) streaming convert
// ---------------------------------------------------------------------------
__global__ void cvt_kernel(const float* __restrict__ in, __half* __restrict__ outp, size_t n4) {
    size_t i = (size_t)blockIdx.x * blockDim.x + threadIdx.x;
    size_t stride = (size_t)gridDim.x * blockDim.x;
    for (; i < n4; i += stride) {
        float4 v = ((const float4*)in)[i];
        ((__half2*)outp)[2 * i]     = __floats2half2_rn(v.x, v.y);
        ((__half2*)outp)[2 * i + 1] = __floats2half2_rn(v.z, v.w);
    }
}

// ---------------------------------------------------------------------------
// fp16 grouped GEMM + GELU.  CTA tile 128x128, BK=64, 3-stage cp.async.
// 128 threads = 4 warps (2M x 2N), warp tile 64x64.
// Pipeline v2: loads for kt+2 issued BEFORE the wait; wait_group<1> leaves the
// newest group in flight -> every load gets ~2 ktiles of latency headroom.
// Barrier publishes stage kt+1; next-kt ks0 fragments prefetched post-barrier
// and hidden under ks3's MMA block.  TWO CTAs per SM.
// MODE 0: A = windowed g_xh[B,P,H] (K=4096, out g_h1h fp16)
// MODE 1: A = g_h1h [p][b][k]      (K=2048, out g_h2  fp32)
// ---------------------------------------------------------------------------
#define BM 128
#define BN 128
#define BK 64
#define ASTRH 72              // A row stride (halves): 144B, LDSM conflict-free
#define BSTRH 136             // B row stride (halves): 272B, LDSM conflict-free
#define ASZB (BM * ASTRH * 2)          // 18432 B
#define BSZB (BK * BSTRH * 2)          // 17408 B
#define STGB (ASZB + BSZB)             // 35840 B / stage
#define NSTG 3
#define SMEM_BYTES (NSTG * STGB)       // 107520

template <int MODE>
__global__ void __launch_bounds__(128, 2)
gemm_f16_kernel(const __half* __restrict__ A, const __half* __restrict__ W,
                const float* __restrict__ bias, void* __restrict__ Cout,
                int K, int N) {
    extern __shared__ __half smem[];
    const uint32_t smem_u = (uint32_t)__cvta_generic_to_shared(smem);

    const int p    = blockIdx.z;
    const int bm   = blockIdx.y;
    const int bn   = blockIdx.x;
    const int tid  = threadIdx.x;
    const int wid  = tid >> 5;
    const int lane = tid & 31;
    const int warpM = wid >> 1;    // 0..1  (64 rows)
    const int warpN = wid & 1;     // 0..1  (64 cols)
    const int g  = lane >> 2;      // 0..7
    const int cc = lane & 3;       // 0..3

    // ldmatrix lane address components
    const int l7 = lane & 7;
    const int lb = (lane >> 3) & 1;
    const int lk = lane >> 4;
    const uint32_t aoff = ((warpM * 64 + lb * 8 + l7) * ASTRH + lk * 8) * 2;
    const uint32_t boff = ASZB + ((lb * 8 + l7) * BSTRH + warpN * 64 + lk * 8) * 2;

    float acc[4][8][4];
#pragma unroll
    for (int mf = 0; mf < 4; mf++)
#pragma unroll
        for (int nf = 0; nf < 8; nf++)
#pragma unroll
            for (int i = 0; i < 4; i++) acc[mf][nf][i] = 0.f;

    const __half* Wp = W + (size_t)p * K * N + (size_t)bn * BN;

    auto load_tiles = [&](int kt, int buf) {
        uint32_t sbase = smem_u + buf * STGB;
        // A: 128 rows x 64 halves = 1024 x 16B chunks -> 8 per thread
#pragma unroll
        for (int i = 0; i < 8; i++) {
            int c  = tid + i * 128;
            int m  = c >> 3;
            int kl = (c & 7) * 8;
            int kg = kt * BK + kl;
            const __half* ga;
            int sz = 16;
            if (MODE == 0) {
                int half_ = (kg >= H_) ? 1 : 0;
                int pp    = p + half_;
                int kk    = kg - half_ * H_;
                if (pp >= P_) { pp = P_ - 1; sz = 0; }   // right-edge zero pad
                ga = A + ((size_t)(bm * BM + m) * P_ + pp) * H_ + kk;
            } else {
                ga = A + ((size_t)p * B_ + bm * BM + m) * (size_t)K + kg;
            }
            cp_async16(sbase + (m * ASTRH + kl) * 2, ga, sz);
        }
        // B: 64 rows x 128 halves = 1024 x 16B chunks -> 8 per thread
#pragma unroll
        for (int i = 0; i < 8; i++) {
            int c  = tid + i * 128;
            int kb = c >> 4;              // 0..63
            int nb = (c & 15) * 8;        // 0..120
            const __half* gb = Wp + (size_t)(kt * BK + kb) * N + nb;
            cp_async16(sbase + ASZB + (kb * BSTRH + nb) * 2, gb, 16);
        }
    };

    uint32_t a[2][4][4], b[2][4][4];

    auto prefetch = [&](uint32_t sbase, int ks, int buf) {
        const uint32_t akk = sbase + aoff + ks * 32;             // +16 halves along k
        const uint32_t bkk = sbase + boff + ks * (16 * BSTRH * 2);
#pragma unroll
        for (int f = 0; f < 4; f++) ldsm4(akk + f * (16 * ASTRH * 2), a[buf][f]);
#pragma unroll
        for (int nf = 0; nf < 4; nf++) ldsm4t(bkk + nf * 32, b[buf][nf]);
    };
    auto mma_block = [&](int buf) {
#pragma unroll
        for (int mf = 0; mf < 4; mf++)
#pragma unroll
            for (int nf = 0; nf < 4; nf++) {
                mma_f16_f32(acc[mf][2 * nf],     a[buf][mf], &b[buf][nf][0]);
                mma_f16_f32(acc[mf][2 * nf + 1], a[buf][mf], &b[buf][nf][2]);
            }
    };

    const int NKT = K / BK;   // >= 16
    load_tiles(0, 0); cp_commit();
    load_tiles(1, 1); cp_commit();
    cp_wait<1>();             // stage 0 complete (stage 1 still in flight)
    __syncthreads();          // stage 0 published
    prefetch(smem_u, 0, 0);   // frags(kt=0, ks=0) -> buf0

    for (int kt = 0; kt < NKT; ++kt) {
        const uint32_t sbase = smem_u + (kt % NSTG) * STGB;

        // ks0..ks2: intra-kt fragment double buffering (ks -> buf[ks&1])
#pragma unroll
        for (int ks = 0; ks < 3; ks++) {
            prefetch(sbase, ks + 1, (ks + 1) & 1);
            mma_block(ks & 1);
        }

        // Issue stage kt+2 loads BEFORE the wait, then leave the newest group
        // in flight: each group gets ~2 ktiles of latency headroom.
        // WAR-safe: buffer (kt+2)%3 == (kt-1)%3; all its reads were issued
        // before the PREVIOUS iteration's barrier.
        if (kt + 2 < NKT) {
            load_tiles(kt + 2, (kt + 2) % NSTG);
            cp_commit();
            cp_wait<1>();     // waits stage kt+1 only
        } else {
            cp_wait<0>();     // tail: drain everything
        }
        __syncthreads();      // publish stage kt+1

        // Post-barrier: prefetch next kt's ks0, hidden under ks3's MMAs.
        if (kt + 1 < NKT) prefetch(smem_u + ((kt + 1) % NSTG) * STGB, 0, 0);

        mma_block(1);   // ks3
    }

    // Epilogue: bias + exact GELU.  MODE0 -> fp16 h1, MODE1 -> fp32 h2.
    const float* brow = bias + (size_t)p * N;
#pragma unroll
    for (int mf = 0; mf < 4; mf++) {
        int row0 = bm * BM + warpM * 64 + mf * 16 + g;
        size_t base0 = ((size_t)p * B_ + row0) * (size_t)N;
        size_t base8 = base0 + (size_t)8 * N;
#pragma unroll
        for (int nf = 0; nf < 8; nf++) {
            int n = bn * BN + warpN * 64 + nf * 8 + cc * 2;
            float bv0 = __ldg(brow + n);
            float bv1 = __ldg(brow + n + 1);
            float v0 = gelu_exact(acc[mf][nf][0] + bv0);
            float v1 = gelu_exact(acc[mf][nf][1] + bv1);
            float v2 = gelu_exact(acc[mf][nf][2] + bv0);
            float v3 = gelu_exact(acc[mf][nf][3] + bv1);
            if (MODE == 0) {
                __half* C = (__half*)Cout;
                *(__half2*)(C + base0 + n) = __floats2half2_rn(v0, v1);
                *(__half2*)(C + base8 + n) = __floats2half2_rn(v2, v3);
            } else {
                float* C = (float*)Cout;
                *(float2*)(C + base0 + n) = make_float2(v0, v1);
                *(float2*)(C + base8 + n) = make_float2(v2, v3);
            }
        }
    }
}

// ---------------------------------------------------------------------------
// Layer 3: out[b, p*4+o] = relu(sum_k h2[p][b][k] * W3[p][k][o] + b3[p][o])
// ---------------------------------------------------------------------------
__global__ void l3_kernel(const float* __restrict__ h2, const float* __restrict__ W3,
                          const float* __restrict__ b3, float* __restrict__ out) {
    int p = blockIdx.x, b = blockIdx.y;
    int tid = threadIdx.x;
    const float* hrow = h2 + ((size_t)p * B_ + b) * N2_;
    const float* w    = W3 + (size_t)p * N2_ * OUTP;

    float a0 = 0.f, a1 = 0.f, a2 = 0.f, a3 = 0.f;
    for (int k = tid; k < N2_; k += 128) {
        float hv = hrow[k];
        const float* wr = w + k * OUTP;
        a0 += hv * wr[0]; a1 += hv * wr[1]; a2 += hv * wr[2]; a3 += hv * wr[3];
    }
#pragma unroll
    for (int off = 16; off; off >>= 1) {
        a0 += __shfl_down_sync(0xffffffffu, a0, off);
        a1 += __shfl_down_sync(0xffffffffu, a1, off);
        a2 += __shfl_down_sync(0xffffffffu, a2, off);
        a3 += __shfl_down_sync(0xffffffffu, a3, off);
    }
    __shared__ float sred[4][4];
    int warp = tid >> 5, lane = tid & 31;
    if (lane == 0) {
        sred[warp][0] = a0; sred[warp][1] = a1; sred[warp][2] = a2; sred[warp][3] = a3;
    }
    __syncthreads();
    if (tid < 4) {
        float s = sred[0][tid] + sred[1][tid] + sred[2][tid] + sred[3][tid]
                + b3[p * OUTP + tid];
        out[(size_t)b * (P_ * OUTP) + p * OUTP + tid] = fmaxf(s, 0.f);
    }
}

// ---------------------------------------------------------------------------
extern "C" void kernel_launch(void* const* d_in, const int* in_sizes, int n_in,
                              void* d_out, int out_size) {
    const float* x  = (const float*)d_in[0];
    const float* W1 = (const float*)d_in[1];
    const float* b1 = (const float*)d_in[2];
    const float* W2 = (const float*)d_in[3];
    const float* b2 = (const float*)d_in[4];
    const float* W3 = (const float*)d_in[5];
    const float* b3 = (const float*)d_in[6];
    float* out = (float*)d_out;

    __half *xh, *w1h, *w2h, *h1h;
    float *h2;
    cudaGetSymbolAddress((void**)&xh,  g_xh);
    cudaGetSymbolAddress((void**)&w1h, g_w1h);
    cudaGetSymbolAddress((void**)&w2h, g_w2h);
    cudaGetSymbolAddress((void**)&h1h, g_h1h);
    cudaGetSymbolAddress((void**)&h2,  g_h2);

    cudaFuncSetAttribute((const void*)gemm_f16_kernel<0>,
                         cudaFuncAttributeMaxDynamicSharedMemorySize, SMEM_BYTES);
    cudaFuncSetAttribute((const void*)gemm_f16_kernel<1>,
                         cudaFuncAttributeMaxDynamicSharedMemorySize, SMEM_BYTES);

    // Prepass: fp32 -> fp16 converts (x, W1, W2)
    cvt_kernel<<<2048, 256>>>(x,  xh,  (size_t)B_ * P_ * H_ / 4);
    cvt_kernel<<<8192, 256>>>(W1, w1h, (size_t)P_ * K1_ * N1_ / 4);
    cvt_kernel<<<4096, 256>>>(W2, w2h, (size_t)P_ * K2_ * N2_ / 4);

    // Layer 1: [1024, 4096] @ [4096, 2048] per p, GELU -> fp16 h1
    gemm_f16_kernel<0><<<dim3(N1_ / BN, B_ / BM, P_), 128, SMEM_BYTES>>>(
        xh, w1h, b1, h1h, K1_, N1_);
    // Layer 2: [1024, 2048] @ [2048, 1024] per p, GELU -> fp32 h2
    gemm_f16_kernel<1><<<dim3(N2_ / BN, B_ / BM, P_), 128, SMEM_BYTES>>>(
        h1h, w2h, b2, h2, K2_, N2_);
    // Layer 3: tiny N=4 + ReLU
    l3_kernel<<<dim3(P_, B_), 128>>>(h2, W3, b3, out);
}

// round 12
// speedup vs baseline: 1.3142x; 1.0786x over previous
#include <cuda_runtime.h>
#include <cuda_fp16.h>
#include <cstdint>

// Problem constants
#define B_   1024
#define P_   24
#define H_   2048
#define K1_  4096   // H*R
#define N1_  2048   // H
#define K2_  2048
#define N2_  1024   // H/2
#define OUTP 4

// Scratch (allocation-free rule: __device__ globals)
__device__ __half g_xh [(size_t)B_ * P_ * H_];    // x   -> fp16
__device__ __half g_w1h[(size_t)P_ * K1_ * N1_];  // W1  -> fp16
__device__ __half g_w2h[(size_t)P_ * K2_ * N2_];  // W2  -> fp16
__device__ __half g_h1h[(size_t)P_ * B_ * N1_];   // layer1 out fp16
__device__ float  g_part[(size_t)P_ * B_ * 8 * OUTP]; // L3 partials [P][B][8][4]

// ---------------------------------------------------------------------------
// helpers
// ---------------------------------------------------------------------------
__device__ __forceinline__ void mma_f16_f32(float* c, const uint32_t* a, const uint32_t* b) {
    asm volatile(
        "mma.sync.aligned.m16n8k16.row.col.f32.f16.f16.f32 "
        "{%0,%1,%2,%3}, {%4,%5,%6,%7}, {%8,%9}, {%0,%1,%2,%3};"
        : "+f"(c[0]), "+f"(c[1]), "+f"(c[2]), "+f"(c[3])
        : "r"(a[0]), "r"(a[1]), "r"(a[2]), "r"(a[3]), "r"(b[0]), "r"(b[1]));
}

__device__ __forceinline__ void ldsm4(uint32_t addr, uint32_t* r) {
    asm volatile("ldmatrix.sync.aligned.m8n8.x4.shared.b16 {%0,%1,%2,%3}, [%4];"
                 : "=r"(r[0]), "=r"(r[1]), "=r"(r[2]), "=r"(r[3]) : "r"(addr));
}
__device__ __forceinline__ void ldsm4t(uint32_t addr, uint32_t* r) {
    asm volatile("ldmatrix.sync.aligned.m8n8.x4.trans.shared.b16 {%0,%1,%2,%3}, [%4];"
                 : "=r"(r[0]), "=r"(r[1]), "=r"(r[2]), "=r"(r[3]) : "r"(addr));
}

__device__ __forceinline__ void cp_async16(uint32_t smem_addr, const void* gptr, int src_size) {
    asm volatile("cp.async.cg.shared.global [%0], [%1], 16, %2;"
                 :: "r"(smem_addr), "l"(gptr), "r"(src_size));
}
__device__ __forceinline__ void cp_commit() {
    asm volatile("cp.async.commit_group;" ::: "memory");
}
template <int N>
__device__ __forceinline__ void cp_wait() {
    asm volatile("cp.async.wait_group %0;" :: "n"(N) : "memory");
}

__device__ __forceinline__ float gelu_exact(float v) {
    return 0.5f * v * (1.0f + erff(v * 0.7071067811865476f));
}

// ---------------------------------------------------------------------------
// Prepass: fp32 -> fp16 (RN) streaming convert
// ---------------------------------------------------------------------------
__global__ void cvt_kernel(const float* __restrict__ in, __half* __restrict__ outp, size_t n4) {
    size_t i = (size_t)blockIdx.x * blockDim.x + threadIdx.x;
    size_t stride = (size_t)gridDim.x * blockDim.x;
    for (; i < n4; i += stride) {
        float4 v = ((const float4*)in)[i];
        ((__half2*)outp)[2 * i]     = __floats2half2_rn(v.x, v.y);
        ((__half2*)outp)[2 * i + 1] = __floats2half2_rn(v.z, v.w);
    }
}

// ---------------------------------------------------------------------------
// fp16 grouped GEMM + GELU.  CTA tile 128x128, BK=64, 3-stage cp.async.
// 128 threads = 4 warps (2M x 2N), warp tile 64x64.
// Pipeline v3: kt+2 loads split across ks0 (A) / ks1 (B) in the MMA shadow;
// wait_group<1> leaves newest group in flight; barrier publishes stage kt+1;
// next-kt ks0 fragments prefetched post-barrier under ks3's MMAs.
// TWO CTAs per SM.  MODE0 skips the zero window half for p = P-1.
// MODE 0: A = windowed g_xh[B,P,H] (K=4096, out g_h1h fp16)
// MODE 1: A = g_h1h [p][b][k]      (K=2048); epilogue fuses layer-3 partial
//         reduction against W3 -> g_part[P][B][8][4] (h2 never materialized)
// ---------------------------------------------------------------------------
#define BM 128
#define BN 128
#define BK 64
#define ASTRH 72              // A row stride (halves): 144B, LDSM conflict-free
#define BSTRH 136             // B row stride (halves): 272B, LDSM conflict-free
#define ASZB (BM * ASTRH * 2)          // 18432 B
#define BSZB (BK * BSTRH * 2)          // 17408 B
#define STGB (ASZB + BSZB)             // 35840 B / stage
#define NSTG 3
#define PIPE_BYTES (NSTG * STGB)       // 107520
#define W3_OFF   PIPE_BYTES            // 2048 B  (128 cols x float4)
#define SRED_OFF (PIPE_BYTES + 2048)   // 4096 B  (128 rows x 4 o x 2 warpN)
#define SMEM_T0  PIPE_BYTES
#define SMEM_T1  (PIPE_BYTES + 2048 + 4096)   // 113664 <= 116736 (2 CTAs)

template <int MODE>
__global__ void __launch_bounds__(128, 2)
gemm_f16_kernel(const __half* __restrict__ A, const __half* __restrict__ W,
                const float* __restrict__ bias, void* __restrict__ Cout,
                const float* __restrict__ W3, int K, int N) {
    extern __shared__ __half smem[];
    char* smem_c = (char*)smem;
    const uint32_t smem_u = (uint32_t)__cvta_generic_to_shared(smem);

    const int p    = blockIdx.z;
    const int bm   = blockIdx.y;
    const int bn   = blockIdx.x;
    const int tid  = threadIdx.x;
    const int wid  = tid >> 5;
    const int lane = tid & 31;
    const int warpM = wid >> 1;    // 0..1  (64 rows)
    const int warpN = wid & 1;     // 0..1  (64 cols)
    const int g  = lane >> 2;      // 0..7
    const int cc = lane & 3;       // 0..3

    // MODE1: stage W3 tile (128 cols x 4 outs) into smem
    if (MODE == 1) {
        const float4* w3g = (const float4*)(W3 + ((size_t)p * N2_ + bn * BN) * OUTP);
        ((float4*)(smem_c + W3_OFF))[tid] = w3g[tid];
    }

    // ldmatrix lane address components
    const int l7 = lane & 7;
    const int lb = (lane >> 3) & 1;
    const int lk = lane >> 4;
    const uint32_t aoff = ((warpM * 64 + lb * 8 + l7) * ASTRH + lk * 8) * 2;
    const uint32_t boff = ASZB + ((lb * 8 + l7) * BSTRH + warpN * 64 + lk * 8) * 2;

    float acc[4][8][4];
#pragma unroll
    for (int mf = 0; mf < 4; mf++)
#pragma unroll
        for (int nf = 0; nf < 8; nf++)
#pragma unroll
            for (int i = 0; i < 4; i++) acc[mf][nf][i] = 0.f;

    const __half* Wp = W + (size_t)p * K * N + (size_t)bn * BN;

    auto load_A = [&](int kt, int buf) {
        uint32_t sbase = smem_u + buf * STGB;
#pragma unroll
        for (int i = 0; i < 8; i++) {
            int c  = tid + i * 128;
            int m  = c >> 3;
            int kl = (c & 7) * 8;
            int kg = kt * BK + kl;
            const __half* ga;
            int sz = 16;
            if (MODE == 0) {
                int half_ = (kg >= H_) ? 1 : 0;
                int pp    = p + half_;
                int kk    = kg - half_ * H_;
                if (pp >= P_) { pp = P_ - 1; sz = 0; }   // right-edge zero pad
                ga = A + ((size_t)(bm * BM + m) * P_ + pp) * H_ + kk;
            } else {
                ga = A + ((size_t)p * B_ + bm * BM + m) * (size_t)K + kg;
            }
            cp_async16(sbase + (m * ASTRH + kl) * 2, ga, sz);
        }
    };
    auto load_B = [&](int kt, int buf) {
        uint32_t sbase = smem_u + buf * STGB;
#pragma unroll
        for (int i = 0; i < 8; i++) {
            int c  = tid + i * 128;
            int kb = c >> 4;              // 0..63
            int nb = (c & 15) * 8;        // 0..120
            const __half* gb = Wp + (size_t)(kt * BK + kb) * N + nb;
            cp_async16(sbase + ASZB + (kb * BSTRH + nb) * 2, gb, 16);
        }
    };

    uint32_t a[2][4][4], b[2][4][4];

    auto prefetch = [&](uint32_t sbase, int ks, int buf) {
        const uint32_t akk = sbase + aoff + ks * 32;             // +16 halves along k
        const uint32_t bkk = sbase + boff + ks * (16 * BSTRH * 2);
#pragma unroll
        for (int f = 0; f < 4; f++) ldsm4(akk + f * (16 * ASTRH * 2), a[buf][f]);
#pragma unroll
        for (int nf = 0; nf < 4; nf++) ldsm4t(bkk + nf * 32, b[buf][nf]);
    };
    auto mma_block = [&](int buf) {
#pragma unroll
        for (int mf = 0; mf < 4; mf++)
#pragma unroll
            for (int nf = 0; nf < 4; nf++) {
                mma_f16_f32(acc[mf][2 * nf],     a[buf][mf], &b[buf][nf][0]);
                mma_f16_f32(acc[mf][2 * nf + 1], a[buf][mf], &b[buf][nf][2]);
            }
    };

    // p = P-1: the second window half is all zeros -> skip it entirely.
    const int NKT = (MODE == 0 && p == P_ - 1) ? (H_ / BK) : (K / BK);   // >= 32

    load_A(0, 0); load_B(0, 0); cp_commit();
    load_A(1, 1); load_B(1, 1); cp_commit();
    cp_wait<1>();             // stage 0 complete (stage 1 still in flight)
    __syncthreads();          // stage 0 published
    prefetch(smem_u, 0, 0);   // frags(kt=0, ks=0) -> buf0

    for (int kt = 0; kt < NKT; ++kt) {
        const uint32_t sbase = smem_u + (kt % NSTG) * STGB;
        const bool more = (kt + 2 < NKT);
        const int  nbuf = (kt + 2) % NSTG;   // WAR-safe: last read before prev barrier

        // ks0: prefetch ks1 frags, issue A loads for kt+2, MMA ks0
        prefetch(sbase, 1, 1);
        if (more) load_A(kt + 2, nbuf);
        mma_block(0);
        // ks1: prefetch ks2 frags, issue B loads for kt+2, MMA ks1
        prefetch(sbase, 2, 0);
        if (more) load_B(kt + 2, nbuf);
        mma_block(1);
        // ks2: prefetch ks3 frags, MMA ks2
        prefetch(sbase, 3, 1);
        mma_block(0);

        if (more) { cp_commit(); cp_wait<1>(); }   // waits stage kt+1 only
        else      { cp_wait<0>(); }                // tail: drain everything
        __syncthreads();                           // publish stage kt+1

        // Post-barrier: prefetch next kt's ks0, hidden under ks3's MMAs.
        if (kt + 1 < NKT) prefetch(smem_u + ((kt + 1) % NSTG) * STGB, 0, 0);

        mma_block(1);   // ks3
    }

    const float* brow = bias + (size_t)p * N;

    if (MODE == 0) {
        // Epilogue: bias + exact GELU -> fp16 h1
        __half* C = (__half*)Cout;
#pragma unroll
        for (int mf = 0; mf < 4; mf++) {
            int row0 = bm * BM + warpM * 64 + mf * 16 + g;
            size_t base0 = ((size_t)p * B_ + row0) * (size_t)N;
            size_t base8 = base0 + (size_t)8 * N;
#pragma unroll
            for (int nf = 0; nf < 8; nf++) {
                int n = bn * BN + warpN * 64 + nf * 8 + cc * 2;
                float bv0 = __ldg(brow + n);
                float bv1 = __ldg(brow + n + 1);
                float v0 = gelu_exact(acc[mf][nf][0] + bv0);
                float v1 = gelu_exact(acc[mf][nf][1] + bv1);
                float v2 = gelu_exact(acc[mf][nf][2] + bv0);
                float v3 = gelu_exact(acc[mf][nf][3] + bv1);
                *(__half2*)(C + base0 + n) = __floats2half2_rn(v0, v1);
                *(__half2*)(C + base8 + n) = __floats2half2_rn(v2, v3);
            }
        }
    } else {
        // Fused epilogue: h2 = gelu(acc + b2); partial[row][o] = sum_c h2 * W3[c][o]
        const float4* w3s = (const float4*)(smem_c + W3_OFF);
        float* sred = (float*)(smem_c + SRED_OFF);   // [128][4][2]
        float pr[8][4];
#pragma unroll
        for (int r = 0; r < 8; r++)
#pragma unroll
            for (int o = 0; o < 4; o++) pr[r][o] = 0.f;

#pragma unroll
        for (int mf = 0; mf < 4; mf++) {
#pragma unroll
            for (int nf = 0; nf < 8; nf++) {
                int ncol = warpN * 64 + nf * 8 + cc * 2;   // local col 0..127
                float bv0 = __ldg(brow + bn * BN + ncol);
                float bv1 = __ldg(brow + bn * BN + ncol + 1);
                float v0 = gelu_exact(acc[mf][nf][0] + bv0);
                float v1 = gelu_exact(acc[mf][nf][1] + bv1);
                float v2 = gelu_exact(acc[mf][nf][2] + bv0);
                float v3 = gelu_exact(acc[mf][nf][3] + bv1);
                float4 wA = w3s[ncol];
                float4 wB = w3s[ncol + 1];
                int r0 = mf * 2, r1 = mf * 2 + 1;
                pr[r0][0] += v0 * wA.x + v1 * wB.x;
                pr[r0][1] += v0 * wA.y + v1 * wB.y;
                pr[r0][2] += v0 * wA.z + v1 * wB.z;
                pr[r0][3] += v0 * wA.w + v1 * wB.w;
                pr[r1][0] += v2 * wA.x + v3 * wB.x;
                pr[r1][1] += v2 * wA.y + v3 * wB.y;
                pr[r1][2] += v2 * wA.z + v3 * wB.z;
                pr[r1][3] += v2 * wA.w + v3 * wB.w;
            }
        }
        // reduce over cc (4-lane groups), deterministic
#pragma unroll
        for (int r = 0; r < 8; r++)
#pragma unroll
            for (int o = 0; o < 4; o++) {
                float v = pr[r][o];
                v += __shfl_xor_sync(0xffffffffu, v, 1);
                v += __shfl_xor_sync(0xffffffffu, v, 2);
                pr[r][o] = v;
            }
        if (cc == 0) {
#pragma unroll
            for (int r = 0; r < 8; r++) {
                int row = warpM * 64 + (r >> 1) * 16 + (r & 1) * 8 + g;
#pragma unroll
                for (int o = 0; o < 4; o++)
                    sred[row * 8 + o * 2 + warpN] = pr[r][o];
            }
        }
        __syncthreads();
        {
            int row = tid;   // 128 threads, 128 rows
            float* part = (float*)Cout;
            size_t base = (((size_t)p * B_ + bm * BM + row) * 8 + bn) * OUTP;
#pragma unroll
            for (int o = 0; o < 4; o++)
                part[base + o] = sred[row * 8 + o * 2] + sred[row * 8 + o * 2 + 1];
        }
    }
}

// ---------------------------------------------------------------------------
// L3 finisher: out[b, p*4+o] = relu(b3[p][o] + sum_{q=0..7} part[p][b][q][o])
// ---------------------------------------------------------------------------
__global__ void l3f_kernel(const float* __restrict__ part, const float* __restrict__ b3,
                           float* __restrict__ out) {
    int idx = blockIdx.x * blockDim.x + threadIdx.x;   // 98304 = 1024*96
    if (idx >= B_ * P_ * OUTP) return;
    int b = idx / (P_ * OUTP);
    int q = idx % (P_ * OUTP);
    int p = q / OUTP;
    int o = q % OUTP;
    const float* pp = part + (((size_t)p * B_ + b) * 8) * OUTP + o;
    float s = b3[p * OUTP + o];
#pragma unroll
    for (int j = 0; j < 8; j++) s += pp[j * OUTP];
    out[idx] = fmaxf(s, 0.f);
}

// ---------------------------------------------------------------------------
extern "C" void kernel_launch(void* const* d_in, const int* in_sizes, int n_in,
                              void* d_out, int out_size) {
    const float* x  = (const float*)d_in[0];
    const float* W1 = (const float*)d_in[1];
    const float* b1 = (const float*)d_in[2];
    const float* W2 = (const float*)d_in[3];
    const float* b2 = (const float*)d_in[4];
    const float* W3 = (const float*)d_in[5];
    const float* b3 = (const float*)d_in[6];
    float* out = (float*)d_out;

    __half *xh, *w1h, *w2h, *h1h;
    float *part;
    cudaGetSymbolAddress((void**)&xh,  g_xh);
    cudaGetSymbolAddress((void**)&w1h, g_w1h);
    cudaGetSymbolAddress((void**)&w2h, g_w2h);
    cudaGetSymbolAddress((void**)&h1h, g_h1h);
    cudaGetSymbolAddress((void**)&part, g_part);

    cudaFuncSetAttribute((const void*)gemm_f16_kernel<0>,
                         cudaFuncAttributeMaxDynamicSharedMemorySize, SMEM_T0);
    cudaFuncSetAttribute((const void*)gemm_f16_kernel<1>,
                         cudaFuncAttributeMaxDynamicSharedMemorySize, SMEM_T1);

    // Prepass: fp32 -> fp16 converts (x, W1, W2)
    cvt_kernel<<<2048, 256>>>(x,  xh,  (size_t)B_ * P_ * H_ / 4);
    cvt_kernel<<<8192, 256>>>(W1, w1h, (size_t)P_ * K1_ * N1_ / 4);
    cvt_kernel<<<4096, 256>>>(W2, w2h, (size_t)P_ * K2_ * N2_ / 4);

    // Layer 1: [1024, 4096] @ [4096, 2048] per p, GELU -> fp16 h1
    gemm_f16_kernel<0><<<dim3(N1_ / BN, B_ / BM, P_), 128, SMEM_T0>>>(
        xh, w1h, b1, h1h, nullptr, K1_, N1_);
    // Layer 2 + fused L3 partials: [1024, 2048] @ [2048, 1024] per p
    gemm_f16_kernel<1><<<dim3(N2_ / BN, B_ / BM, P_), 128, SMEM_T1>>>(
        h1h, w2h, b2, part, W3, K2_, N2_);
    // L3 finisher: sum partials + bias + ReLU
    l3f_kernel<<<(B_ * P_ * OUTP + 255) / 256, 256>>>(part, b3, out);
}

// round 13
// speedup vs baseline: 1.3363x; 1.0168x over previous
#include <cuda_runtime.h>
#include <cuda_fp16.h>
#include <cstdint>

// Problem constants
#define B_   1024
#define P_   24
#define H_   2048
#define K1_  4096   // H*R
#define N1_  2048   // H
#define K2_  2048
#define N2_  1024   // H/2
#define OUTP 4

// Scratch (allocation-free rule: __device__ globals)
__device__ __half g_xh [(size_t)B_ * P_ * H_];    // x   -> fp16
__device__ __half g_w1h[(size_t)P_ * K1_ * N1_];  // W1  -> fp16
__device__ __half g_w2h[(size_t)P_ * K2_ * N2_];  // W2  -> fp16
__device__ __half g_h1h[(size_t)P_ * B_ * N1_];   // layer1 out fp16
__device__ float  g_part[(size_t)P_ * B_ * 8 * OUTP]; // L3 partials [P][B][8][4]
__device__ unsigned g_ctr[2];                     // persistent tile counters

// ---------------------------------------------------------------------------
// helpers
// ---------------------------------------------------------------------------
__device__ __forceinline__ void mma_f16_f32(float* c, const uint32_t* a, const uint32_t* b) {
    asm volatile(
        "mma.sync.aligned.m16n8k16.row.col.f32.f16.f16.f32 "
        "{%0,%1,%2,%3}, {%4,%5,%6,%7}, {%8,%9}, {%0,%1,%2,%3};"
        : "+f"(c[0]), "+f"(c[1]), "+f"(c[2]), "+f"(c[3])
        : "r"(a[0]), "r"(a[1]), "r"(a[2]), "r"(a[3]), "r"(b[0]), "r"(b[1]));
}

__device__ __forceinline__ void ldsm4(uint32_t addr, uint32_t* r) {
    asm volatile("ldmatrix.sync.aligned.m8n8.x4.shared.b16 {%0,%1,%2,%3}, [%4];"
                 : "=r"(r[0]), "=r"(r[1]), "=r"(r[2]), "=r"(r[3]) : "r"(addr));
}
__device__ __forceinline__ void ldsm4t(uint32_t addr, uint32_t* r) {
    asm volatile("ldmatrix.sync.aligned.m8n8.x4.trans.shared.b16 {%0,%1,%2,%3}, [%4];"
                 : "=r"(r[0]), "=r"(r[1]), "=r"(r[2]), "=r"(r[3]) : "r"(addr));
}

__device__ __forceinline__ void cp_async16(uint32_t smem_addr, const void* gptr, int src_size) {
    asm volatile("cp.async.cg.shared.global [%0], [%1], 16, %2;"
                 :: "r"(smem_addr), "l"(gptr), "r"(src_size));
}
__device__ __forceinline__ void cp_commit() {
    asm volatile("cp.async.commit_group;" ::: "memory");
}
template <int N>
__device__ __forceinline__ void cp_wait() {
    asm volatile("cp.async.wait_group %0;" :: "n"(N) : "memory");
}

__device__ __forceinline__ float gelu_exact(float v) {
    return 0.5f * v * (1.0f + erff(v * 0.7071067811865476f));
}

// ---------------------------------------------------------------------------
// reset: zero persistent counters (first node of every graph replay)
// ---------------------------------------------------------------------------
__global__ void reset_kernel() { g_ctr[0] = 0; g_ctr[1] = 0; }

// ---------------------------------------------------------------------------
// Prepass: fp32 -> fp16 (RN) streaming convert (x and W1 only; W2 fused into GEMM1)
// ---------------------------------------------------------------------------
__global__ void cvt_kernel(const float* __restrict__ in, __half* __restrict__ outp, size_t n4) {
    size_t i = (size_t)blockIdx.x * blockDim.x + threadIdx.x;
    size_t stride = (size_t)gridDim.x * blockDim.x;
    for (; i < n4; i += stride) {
        float4 v = ((const float4*)in)[i];
        ((__half2*)outp)[2 * i]     = __floats2half2_rn(v.x, v.y);
        ((__half2*)outp)[2 * i + 1] = __floats2half2_rn(v.z, v.w);
    }
}

// ---------------------------------------------------------------------------
// fp16 grouped GEMM + GELU.  CTA tile 128x128, BK=64, 3-stage cp.async.
// 128 threads = 4 warps (2M x 2N), warp tile 64x64, pipeline v3 (R12).
// PERSISTENT: grid = 2 CTAs/SM; tiles claimed via atomic counter (deterministic:
// every tile's computation and output location are independent of claim order).
// MODE 0: A = windowed g_xh[B,P,H] (K=4096, out g_h1h fp16); per tile also
//         converts a 4096-float4 slice of W2 fp32->fp16 (overlapped side job).
// MODE 1: A = g_h1h; epilogue fuses L3 partial reduction -> g_part (no h2).
// ---------------------------------------------------------------------------
#define BM 128
#define BN 128
#define BK 64
#define ASTRH 72              // A row stride (halves): 144B, LDSM conflict-free
#define BSTRH 136             // B row stride (halves): 272B, LDSM conflict-free
#define ASZB (BM * ASTRH * 2)          // 18432 B
#define BSZB (BK * BSTRH * 2)          // 17408 B
#define STGB (ASZB + BSZB)             // 35840 B / stage
#define NSTG 3
#define PIPE_BYTES (NSTG * STGB)       // 107520
#define W3_OFF   PIPE_BYTES            // 2048 B  (128 cols x float4)
#define SRED_OFF (PIPE_BYTES + 2048)   // 4096 B
#define SMEM_T0  PIPE_BYTES
#define SMEM_T1  (PIPE_BYTES + 2048 + 4096)   // 113664

#define NT0 (16 * 8 * P_)   // 3072 tiles  (bn 16, bm 8, p 24)
#define NT1 (8 * 8 * P_)    // 1536 tiles  (bn 8,  bm 8, p 24)

template <int MODE>
__global__ void __launch_bounds__(128, 2)
gemm_f16_kernel(const __half* __restrict__ A, const __half* __restrict__ W,
                const float* __restrict__ bias, void* __restrict__ Cout,
                const float* __restrict__ W3,
                const float4* __restrict__ w2src, __half2* __restrict__ w2dst,
                int K, int N) {
    extern __shared__ __half smem[];
    char* smem_c = (char*)smem;
    const uint32_t smem_u = (uint32_t)__cvta_generic_to_shared(smem);
    __shared__ int s_tile;

    const int tid  = threadIdx.x;
    const int wid  = tid >> 5;
    const int lane = tid & 31;
    const int warpM = wid >> 1;    // 0..1  (64 rows)
    const int warpN = wid & 1;     // 0..1  (64 cols)
    const int g  = lane >> 2;      // 0..7
    const int cc = lane & 3;       // 0..3

    // ldmatrix lane address components
    const int l7 = lane & 7;
    const int lb = (lane >> 3) & 1;
    const int lk = lane >> 4;
    const uint32_t aoff = ((warpM * 64 + lb * 8 + l7) * ASTRH + lk * 8) * 2;
    const uint32_t boff = ASZB + ((lb * 8 + l7) * BSTRH + warpN * 64 + lk * 8) * 2;

    const int numTiles = (MODE == 0) ? NT0 : NT1;

    while (true) {
        if (tid == 0) s_tile = (int)atomicAdd(&g_ctr[MODE], 1u);
        __syncthreads();
        const int t = s_tile;
        if (t >= numTiles) break;

        int bn, bm, p;
        if (MODE == 0) { bn = t & 15; bm = (t >> 4) & 7; p = t >> 7; }
        else           { bn = t & 7;  bm = (t >> 3) & 7; p = t >> 6; }

        // MODE1: stage W3 tile (128 cols x 4 outs) into smem
        if (MODE == 1) {
            const float4* w3g = (const float4*)(W3 + ((size_t)p * N2_ + bn * BN) * OUTP);
            ((float4*)(smem_c + W3_OFF))[tid] = w3g[tid];
        }

        float acc[4][8][4];
#pragma unroll
        for (int mf = 0; mf < 4; mf++)
#pragma unroll
            for (int nf = 0; nf < 8; nf++)
#pragma unroll
                for (int i = 0; i < 4; i++) acc[mf][nf][i] = 0.f;

        const __half* Wp = W + (size_t)p * K * N + (size_t)bn * BN;

        auto load_A = [&](int kt, int buf) {
            uint32_t sbase = smem_u + buf * STGB;
#pragma unroll
            for (int i = 0; i < 8; i++) {
                int c  = tid + i * 128;
                int m  = c >> 3;
                int kl = (c & 7) * 8;
                int kg = kt * BK + kl;
                const __half* ga;
                int sz = 16;
                if (MODE == 0) {
                    int half_ = (kg >= H_) ? 1 : 0;
                    int pp    = p + half_;
                    int kk    = kg - half_ * H_;
                    if (pp >= P_) { pp = P_ - 1; sz = 0; }   // right-edge zero pad
                    ga = A + ((size_t)(bm * BM + m) * P_ + pp) * H_ + kk;
                } else {
                    ga = A + ((size_t)p * B_ + bm * BM + m) * (size_t)K + kg;
                }
                cp_async16(sbase + (m * ASTRH + kl) * 2, ga, sz);
            }
        };
        auto load_B = [&](int kt, int buf) {
            uint32_t sbase = smem_u + buf * STGB;
#pragma unroll
            for (int i = 0; i < 8; i++) {
                int c  = tid + i * 128;
                int kb = c >> 4;              // 0..63
                int nb = (c & 15) * 8;        // 0..120
                const __half* gb = Wp + (size_t)(kt * BK + kb) * N + nb;
                cp_async16(sbase + ASZB + (kb * BSTRH + nb) * 2, gb, 16);
            }
        };

        uint32_t a[2][4][4], b[2][4][4];

        auto prefetch = [&](uint32_t sbase, int ks, int buf) {
            const uint32_t akk = sbase + aoff + ks * 32;
            const uint32_t bkk = sbase + boff + ks * (16 * BSTRH * 2);
#pragma unroll
            for (int f = 0; f < 4; f++) ldsm4(akk + f * (16 * ASTRH * 2), a[buf][f]);
#pragma unroll
            for (int nf = 0; nf < 4; nf++) ldsm4t(bkk + nf * 32, b[buf][nf]);
        };
        auto mma_block = [&](int buf) {
#pragma unroll
            for (int mf = 0; mf < 4; mf++)
#pragma unroll
                for (int nf = 0; nf < 4; nf++) {
                    mma_f16_f32(acc[mf][2 * nf],     a[buf][mf], &b[buf][nf][0]);
                    mma_f16_f32(acc[mf][2 * nf + 1], a[buf][mf], &b[buf][nf][2]);
                }
        };

        // p = P-1: the second window half is all zeros -> skip it entirely.
        const int NKT = (MODE == 0 && p == P_ - 1) ? (H_ / BK) : (K / BK);

        load_A(0, 0); load_B(0, 0); cp_commit();
        load_A(1, 1); load_B(1, 1); cp_commit();
        cp_wait<1>();
        __syncthreads();
        prefetch(smem_u, 0, 0);

        for (int kt = 0; kt < NKT; ++kt) {
            const uint32_t sbase = smem_u + (kt % NSTG) * STGB;
            const bool more = (kt + 2 < NKT);
            const int  nbuf = (kt + 2) % NSTG;

            prefetch(sbase, 1, 1);
            if (more) load_A(kt + 2, nbuf);
            mma_block(0);
            prefetch(sbase, 2, 0);
            if (more) load_B(kt + 2, nbuf);
            mma_block(1);
            prefetch(sbase, 3, 1);
            mma_block(0);

            if (more) { cp_commit(); cp_wait<1>(); }
            else      { cp_wait<0>(); }
            __syncthreads();

            if (kt + 1 < NKT) prefetch(smem_u + ((kt + 1) % NSTG) * STGB, 0, 0);

            mma_block(1);   // ks3
        }

        const float* brow = bias + (size_t)p * N;

        if (MODE == 0) {
            // Epilogue: bias + exact GELU -> fp16 h1
            __half* C = (__half*)Cout;
#pragma unroll
            for (int mf = 0; mf < 4; mf++) {
                int row0 = bm * BM + warpM * 64 + mf * 16 + g;
                size_t base0 = ((size_t)p * B_ + row0) * (size_t)N;
                size_t base8 = base0 + (size_t)8 * N;
#pragma unroll
                for (int nf = 0; nf < 8; nf++) {
                    int n = bn * BN + warpN * 64 + nf * 8 + cc * 2;
                    float bv0 = __ldg(brow + n);
                    float bv1 = __ldg(brow + n + 1);
                    float v0 = gelu_exact(acc[mf][nf][0] + bv0);
                    float v1 = gelu_exact(acc[mf][nf][1] + bv1);
                    float v2 = gelu_exact(acc[mf][nf][2] + bv0);
                    float v3 = gelu_exact(acc[mf][nf][3] + bv1);
                    *(__half2*)(C + base0 + n) = __floats2half2_rn(v0, v1);
                    *(__half2*)(C + base8 + n) = __floats2half2_rn(v2, v3);
                }
            }
            // Side job: convert this tile's W2 slice fp32 -> fp16
            // (tile t owns float4 range [t*4096, (t+1)*4096); 3072*4096 covers all)
            {
                size_t base = (size_t)t * 4096 + tid;
#pragma unroll 4
                for (int i = 0; i < 32; i++) {
                    size_t idx = base + (size_t)i * 128;
                    float4 v = __ldg(&w2src[idx]);
                    w2dst[2 * idx]     = __floats2half2_rn(v.x, v.y);
                    w2dst[2 * idx + 1] = __floats2half2_rn(v.z, v.w);
                }
            }
        } else {
            // Fused epilogue: h2 = gelu(acc + b2); partial[row][o] = sum_c h2 * W3[c][o]
            const float4* w3s = (const float4*)(smem_c + W3_OFF);
            float* sred = (float*)(smem_c + SRED_OFF);   // [128][4][2]
            float pr[8][4];
#pragma unroll
            for (int r = 0; r < 8; r++)
#pragma unroll
                for (int o = 0; o < 4; o++) pr[r][o] = 0.f;

#pragma unroll
            for (int mf = 0; mf < 4; mf++) {
#pragma unroll
                for (int nf = 0; nf < 8; nf++) {
                    int ncol = warpN * 64 + nf * 8 + cc * 2;
                    float bv0 = __ldg(brow + bn * BN + ncol);
                    float bv1 = __ldg(brow + bn * BN + ncol + 1);
                    float v0 = gelu_exact(acc[mf][nf][0] + bv0);
                    float v1 = gelu_exact(acc[mf][nf][1] + bv1);
                    float v2 = gelu_exact(acc[mf][nf][2] + bv0);
                    float v3 = gelu_exact(acc[mf][nf][3] + bv1);
                    float4 wA = w3s[ncol];
                    float4 wB = w3s[ncol + 1];
                    int r0 = mf * 2, r1 = mf * 2 + 1;
                    pr[r0][0] += v0 * wA.x + v1 * wB.x;
                    pr[r0][1] += v0 * wA.y + v1 * wB.y;
                    pr[r0][2] += v0 * wA.z + v1 * wB.z;
                    pr[r0][3] += v0 * wA.w + v1 * wB.w;
                    pr[r1][0] += v2 * wA.x + v3 * wB.x;
                    pr[r1][1] += v2 * wA.y + v3 * wB.y;
                    pr[r1][2] += v2 * wA.z + v3 * wB.z;
                    pr[r1][3] += v2 * wA.w + v3 * wB.w;
                }
            }
#pragma unroll
            for (int r = 0; r < 8; r++)
#pragma unroll
                for (int o = 0; o < 4; o++) {
                    float v = pr[r][o];
                    v += __shfl_xor_sync(0xffffffffu, v, 1);
                    v += __shfl_xor_sync(0xffffffffu, v, 2);
                    pr[r][o] = v;
                }
            if (cc == 0) {
#pragma unroll
                for (int r = 0; r < 8; r++) {
                    int row = warpM * 64 + (r >> 1) * 16 + (r & 1) * 8 + g;
#pragma unroll
                    for (int o = 0; o < 4; o++)
                        sred[row * 8 + o * 2 + warpN] = pr[r][o];
                }
            }
            __syncthreads();
            {
                int row = tid;
                float* part = (float*)Cout;
                size_t base = (((size_t)p * B_ + bm * BM + row) * 8 + bn) * OUTP;
#pragma unroll
                for (int o = 0; o < 4; o++)
                    part[base + o] = sred[row * 8 + o * 2] + sred[row * 8 + o * 2 + 1];
            }
        }
    }
}

// ---------------------------------------------------------------------------
// L3 finisher: out[b, p*4+o] = relu(b3[p][o] + sum_{q=0..7} part[p][b][q][o])
// ---------------------------------------------------------------------------
__global__ void l3f_kernel(const float* __restrict__ part, const float* __restrict__ b3,
                           float* __restrict__ out) {
    int idx = blockIdx.x * blockDim.x + threadIdx.x;
    if (idx >= B_ * P_ * OUTP) return;
    int b = idx / (P_ * OUTP);
    int q = idx % (P_ * OUTP);
    int p = q / OUTP;
    int o = q % OUTP;
    const float* pp = part + (((size_t)p * B_ + b) * 8) * OUTP + o;
    float s = b3[p * OUTP + o];
#pragma unroll
    for (int j = 0; j < 8; j++) s += pp[j * OUTP];
    out[idx] = fmaxf(s, 0.f);
}

// ---------------------------------------------------------------------------
extern "C" void kernel_launch(void* const* d_in, const int* in_sizes, int n_in,
                              void* d_out, int out_size) {
    const float* x  = (const float*)d_in[0];
    const float* W1 = (const float*)d_in[1];
    const float* b1 = (const float*)d_in[2];
    const float* W2 = (const float*)d_in[3];
    const float* b2 = (const float*)d_in[4];
    const float* W3 = (const float*)d_in[5];
    const float* b3 = (const float*)d_in[6];
    float* out = (float*)d_out;

    __half *xh, *w1h, *w2h, *h1h;
    float *part;
    cudaGetSymbolAddress((void**)&xh,  g_xh);
    cudaGetSymbolAddress((void**)&w1h, g_w1h);
    cudaGetSymbolAddress((void**)&w2h, g_w2h);
    cudaGetSymbolAddress((void**)&h1h, g_h1h);
    cudaGetSymbolAddress((void**)&part, g_part);

    int smCount = 148;
    cudaDeviceGetAttribute(&smCount, cudaDevAttrMultiProcessorCount, 0);
    const int nCTA = 2 * smCount;

    cudaFuncSetAttribute((const void*)gemm_f16_kernel<0>,
                         cudaFuncAttributeMaxDynamicSharedMemorySize, SMEM_T0);
    cudaFuncSetAttribute((const void*)gemm_f16_kernel<1>,
                         cudaFuncAttributeMaxDynamicSharedMemorySize, SMEM_T1);

    // Reset persistent counters (must be first each replay)
    reset_kernel<<<1, 1>>>();

    // Prepass: fp32 -> fp16 converts (x, W1); W2 conversion is fused into GEMM1
    cvt_kernel<<<2048, 256>>>(x,  xh,  (size_t)B_ * P_ * H_ / 4);
    cvt_kernel<<<8192, 256>>>(W1, w1h, (size_t)P_ * K1_ * N1_ / 4);

    // Layer 1 (persistent): windowed [1024,4096]@[4096,2048] per p, GELU -> fp16 h1
    gemm_f16_kernel<0><<<nCTA, 128, SMEM_T0>>>(
        xh, w1h, b1, h1h, nullptr, (const float4*)W2, (__half2*)w2h, K1_, N1_);
    // Layer 2 + fused L3 partials (persistent)
    gemm_f16_kernel<1><<<nCTA, 128, SMEM_T1>>>(
        h1h, w2h, b2, part, W3, nullptr, nullptr, K2_, N2_);
    // L3 finisher
    l3f_kernel<<<(B_ * P_ * OUTP + 255) / 256, 256>>>(part, b3, out);
}

// round 14
// speedup vs baseline: 1.3485x; 1.0091x over previous
#include <cuda_runtime.h>
#include <cuda_fp16.h>
#include <cstdint>

// Problem constants
#define B_   1024
#define P_   24
#define H_   2048
#define K1_  4096   // H*R
#define N1_  2048   // H
#define K2_  2048
#define N2_  1024   // H/2
#define OUTP 4

// Scratch (allocation-free rule: __device__ globals)
__device__ __half g_xh [(size_t)B_ * P_ * H_];    // x   -> fp16
__device__ __half g_w1h[(size_t)P_ * K1_ * N1_];  // W1  -> fp16
__device__ __half g_w2h[(size_t)P_ * K2_ * N2_];  // W2  -> fp16
__device__ __half g_h1h[(size_t)P_ * B_ * N1_];   // layer1 out fp16
__device__ float  g_part[(size_t)P_ * B_ * 8 * OUTP]; // L3 partials [P][B][8][4]
__device__ unsigned g_qctr;                       // work-queue counter
__device__ unsigned g_cnt_x;                      // x cvt completions
__device__ unsigned g_cnt_w1[P_];                 // W1 cvt completions per p
__device__ unsigned g_cnt_g1[P_];                 // GEMM1 tile completions per p

// ---------------------------------------------------------------------------
// helpers
// ---------------------------------------------------------------------------
__device__ __forceinline__ void mma_f16_f32(float* c, const uint32_t* a, const uint32_t* b) {
    asm volatile(
        "mma.sync.aligned.m16n8k16.row.col.f32.f16.f16.f32 "
        "{%0,%1,%2,%3}, {%4,%5,%6,%7}, {%8,%9}, {%0,%1,%2,%3};"
        : "+f"(c[0]), "+f"(c[1]), "+f"(c[2]), "+f"(c[3])
        : "r"(a[0]), "r"(a[1]), "r"(a[2]), "r"(a[3]), "r"(b[0]), "r"(b[1]));
}

__device__ __forceinline__ void ldsm4(uint32_t addr, uint32_t* r) {
    asm volatile("ldmatrix.sync.aligned.m8n8.x4.shared.b16 {%0,%1,%2,%3}, [%4];"
                 : "=r"(r[0]), "=r"(r[1]), "=r"(r[2]), "=r"(r[3]) : "r"(addr));
}
__device__ __forceinline__ void ldsm4t(uint32_t addr, uint32_t* r) {
    asm volatile("ldmatrix.sync.aligned.m8n8.x4.trans.shared.b16 {%0,%1,%2,%3}, [%4];"
                 : "=r"(r[0]), "=r"(r[1]), "=r"(r[2]), "=r"(r[3]) : "r"(addr));
}

__device__ __forceinline__ void cp_async16(uint32_t smem_addr, const void* gptr, int src_size) {
    asm volatile("cp.async.cg.shared.global [%0], [%1], 16, %2;"
                 :: "r"(smem_addr), "l"(gptr), "r"(src_size));
}
__device__ __forceinline__ void cp_commit() {
    asm volatile("cp.async.commit_group;" ::: "memory");
}
template <int N>
__device__ __forceinline__ void cp_wait() {
    asm volatile("cp.async.wait_group %0;" :: "n"(N) : "memory");
}

__device__ __forceinline__ float gelu_exact(float v) {
    return 0.5f * v * (1.0f + erff(v * 0.7071067811865476f));
}

__device__ __forceinline__ unsigned ld_acq(const unsigned* p) {
    unsigned v;
    asm volatile("ld.acquire.gpu.u32 %0, [%1];" : "=r"(v) : "l"(p));
    return v;
}

// ---------------------------------------------------------------------------
// reset: zero all counters (first node of every replay)
// ---------------------------------------------------------------------------
__global__ void reset_kernel() {
    g_qctr = 0; g_cnt_x = 0;
    for (int i = 0; i < P_; i++) { g_cnt_w1[i] = 0; g_cnt_g1[i] = 0; }
}

// ---------------------------------------------------------------------------
// Work queue layout (single monotonic counter):
//   [0, XITEMS)                          : x fp32->fp16 chunks
//   [XITEMS + p*SEG, +W1ITEMS)           : W1[p] fp32->fp16 chunks
//   [XITEMS + p*SEG + W1ITEMS, +128)     : GEMM1 tiles for p (waits x, W1[p])
//   [G2BASE + p*64, +64)                 : GEMM2 tiles for p (waits g1[p]==128)
// Deadlock-free: claims are monotonic; a spinning CTA never blocks claims by
// others, and every earlier-claimed item completes unconditionally.
// Deterministic: every item's output is independent of claim order.
// ---------------------------------------------------------------------------
#define XITEMS   768
#define XF4      16384     // float4 per x item   (768*16384 = 12.58M = B*P*H/4)
#define W1ITEMS  128
#define W1F4     16384     // float4 per W1 item  (128*16384 = K1*N1/4)
#define SEG      (W1ITEMS + 128)            // 256
#define G2BASE   (XITEMS + P_ * SEG)        // 6912
#define NITEMS   (G2BASE + P_ * 64)         // 8448

#define BM 128
#define BN 128
#define BK 64
#define ASTRH 72
#define BSTRH 136
#define ASZB (BM * ASTRH * 2)          // 18432 B
#define BSZB (BK * BSTRH * 2)          // 17408 B
#define STGB (ASZB + BSZB)             // 35840 B / stage
#define NSTG 3
#define PIPE_BYTES (NSTG * STGB)       // 107520
#define W3_OFF   PIPE_BYTES
#define SRED_OFF (PIPE_BYTES + 2048)
#define SMEM_ALL (PIPE_BYTES + 2048 + 4096)   // 113664

__global__ void __launch_bounds__(128, 2)
mega_kernel(const float* __restrict__ x,  const float* __restrict__ W1,
            const float* __restrict__ b1, const float* __restrict__ W2,
            const float* __restrict__ b2, const float* __restrict__ W3,
            __half* __restrict__ xh, __half* __restrict__ w1h,
            __half* __restrict__ w2h, __half* __restrict__ h1h,
            float* __restrict__ part) {
    extern __shared__ __half smem[];
    char* smem_c = (char*)smem;
    const uint32_t smem_u = (uint32_t)__cvta_generic_to_shared(smem);
    __shared__ int s_tile;

    const int tid  = threadIdx.x;
    const int wid  = tid >> 5;
    const int lane = tid & 31;
    const int warpM = wid >> 1;
    const int warpN = wid & 1;
    const int g  = lane >> 2;
    const int cc = lane & 3;

    const int l7 = lane & 7;
    const int lb = (lane >> 3) & 1;
    const int lk = lane >> 4;
    const uint32_t aoff = ((warpM * 64 + lb * 8 + l7) * ASTRH + lk * 8) * 2;
    const uint32_t boff = ASZB + ((lb * 8 + l7) * BSTRH + warpN * 64 + lk * 8) * 2;

    while (true) {
        if (tid == 0) s_tile = (int)atomicAdd(&g_qctr, 1u);
        __syncthreads();
        const int item = s_tile;
        if (item >= NITEMS) break;

        // ------------------------------------------------------------------
        // x convert item
        // ------------------------------------------------------------------
        if (item < XITEMS) {
            size_t base = (size_t)item * XF4 + tid;
            const float4* src = (const float4*)x;
            __half2* dst = (__half2*)xh;
#pragma unroll 8
            for (int i = 0; i < XF4 / 128; i++) {
                size_t idx = base + (size_t)i * 128;
                float4 v = __ldg(&src[idx]);
                dst[2 * idx]     = __floats2half2_rn(v.x, v.y);
                dst[2 * idx + 1] = __floats2half2_rn(v.z, v.w);
            }
            __threadfence(); __syncthreads();
            if (tid == 0) atomicAdd(&g_cnt_x, 1u);
            continue;
        }

        if (item < G2BASE) {
            const int r = item - XITEMS;
            const int p = r / SEG;
            const int s = r % SEG;

            // --------------------------------------------------------------
            // W1[p] convert item
            // --------------------------------------------------------------
            if (s < W1ITEMS) {
                size_t base = (size_t)p * (W1ITEMS * (size_t)W1F4)
                            + (size_t)s * W1F4 + tid;
                const float4* src = (const float4*)W1;
                __half2* dst = (__half2*)w1h;
#pragma unroll 8
                for (int i = 0; i < W1F4 / 128; i++) {
                    size_t idx = base + (size_t)i * 128;
                    float4 v = __ldg(&src[idx]);
                    dst[2 * idx]     = __floats2half2_rn(v.x, v.y);
                    dst[2 * idx + 1] = __floats2half2_rn(v.z, v.w);
                }
                __threadfence(); __syncthreads();
                if (tid == 0) atomicAdd(&g_cnt_w1[p], 1u);
                continue;
            }

            // --------------------------------------------------------------
            // GEMM1 tile (p, bm, bn): h1 = gelu(Xw @ W1 + b1), + W2 cvt side job
            // --------------------------------------------------------------
            const int tl = s - W1ITEMS;          // 0..127
            const int bn = tl & 15, bm = tl >> 4;
            if (tid == 0) {
                while (ld_acq(&g_cnt_x) < XITEMS) __nanosleep(64);
                while (ld_acq(&g_cnt_w1[p]) < W1ITEMS) __nanosleep(64);
            }
            __syncthreads();

            float acc[4][8][4];
#pragma unroll
            for (int mf = 0; mf < 4; mf++)
#pragma unroll
                for (int nf = 0; nf < 8; nf++)
#pragma unroll
                    for (int i = 0; i < 4; i++) acc[mf][nf][i] = 0.f;

            const __half* Wp = w1h + (size_t)p * K1_ * N1_ + (size_t)bn * BN;

            auto load_A = [&](int kt, int buf) {
                uint32_t sbase = smem_u + buf * STGB;
#pragma unroll
                for (int i = 0; i < 8; i++) {
                    int c  = tid + i * 128;
                    int m  = c >> 3;
                    int kl = (c & 7) * 8;
                    int kg = kt * BK + kl;
                    int half_ = (kg >= H_) ? 1 : 0;
                    int pp    = p + half_;
                    int kk    = kg - half_ * H_;
                    int sz = 16;
                    if (pp >= P_) { pp = P_ - 1; sz = 0; }
                    const __half* ga = xh + ((size_t)(bm * BM + m) * P_ + pp) * H_ + kk;
                    cp_async16(sbase + (m * ASTRH + kl) * 2, ga, sz);
                }
            };
            auto load_B = [&](int kt, int buf) {
                uint32_t sbase = smem_u + buf * STGB;
#pragma unroll
                for (int i = 0; i < 8; i++) {
                    int c  = tid + i * 128;
                    int kb = c >> 4;
                    int nb = (c & 15) * 8;
                    const __half* gb = Wp + (size_t)(kt * BK + kb) * N1_ + nb;
                    cp_async16(sbase + ASZB + (kb * BSTRH + nb) * 2, gb, 16);
                }
            };

            uint32_t a[2][4][4], b[2][4][4];
            auto prefetch = [&](uint32_t sbase, int ks, int buf) {
                const uint32_t akk = sbase + aoff + ks * 32;
                const uint32_t bkk = sbase + boff + ks * (16 * BSTRH * 2);
#pragma unroll
                for (int f = 0; f < 4; f++) ldsm4(akk + f * (16 * ASTRH * 2), a[buf][f]);
#pragma unroll
                for (int nf = 0; nf < 4; nf++) ldsm4t(bkk + nf * 32, b[buf][nf]);
            };
            auto mma_block = [&](int buf) {
#pragma unroll
                for (int mf = 0; mf < 4; mf++)
#pragma unroll
                    for (int nf = 0; nf < 4; nf++) {
                        mma_f16_f32(acc[mf][2 * nf],     a[buf][mf], &b[buf][nf][0]);
                        mma_f16_f32(acc[mf][2 * nf + 1], a[buf][mf], &b[buf][nf][2]);
                    }
            };

            const int NKT = (p == P_ - 1) ? (H_ / BK) : (K1_ / BK);

            load_A(0, 0); load_B(0, 0); cp_commit();
            load_A(1, 1); load_B(1, 1); cp_commit();
            cp_wait<1>(); __syncthreads();
            prefetch(smem_u, 0, 0);

            for (int kt = 0; kt < NKT; ++kt) {
                const uint32_t sbase = smem_u + (kt % NSTG) * STGB;
                const bool more = (kt + 2 < NKT);
                const int  nbuf = (kt + 2) % NSTG;

                prefetch(sbase, 1, 1);
                if (more) load_A(kt + 2, nbuf);
                mma_block(0);
                prefetch(sbase, 2, 0);
                if (more) load_B(kt + 2, nbuf);
                mma_block(1);
                prefetch(sbase, 3, 1);
                mma_block(0);

                if (more) { cp_commit(); cp_wait<1>(); }
                else      { cp_wait<0>(); }
                __syncthreads();
                if (kt + 1 < NKT) prefetch(smem_u + ((kt + 1) % NSTG) * STGB, 0, 0);
                mma_block(1);
            }

            const float* brow = b1 + (size_t)p * N1_;
#pragma unroll
            for (int mf = 0; mf < 4; mf++) {
                int row0 = bm * BM + warpM * 64 + mf * 16 + g;
                size_t base0 = ((size_t)p * B_ + row0) * (size_t)N1_;
                size_t base8 = base0 + (size_t)8 * N1_;
#pragma unroll
                for (int nf = 0; nf < 8; nf++) {
                    int n = bn * BN + warpN * 64 + nf * 8 + cc * 2;
                    float bv0 = __ldg(brow + n);
                    float bv1 = __ldg(brow + n + 1);
                    float v0 = gelu_exact(acc[mf][nf][0] + bv0);
                    float v1 = gelu_exact(acc[mf][nf][1] + bv1);
                    float v2 = gelu_exact(acc[mf][nf][2] + bv0);
                    float v3 = gelu_exact(acc[mf][nf][3] + bv1);
                    *(__half2*)(h1h + base0 + n) = __floats2half2_rn(v0, v1);
                    *(__half2*)(h1h + base8 + n) = __floats2half2_rn(v2, v3);
                }
            }
            // Side job: convert W2 slice; global g1 tile id = p*128 + tl covers all of W2
            {
                size_t base = ((size_t)p * 128 + tl) * 4096 + tid;
                const float4* w2src = (const float4*)W2;
                __half2* w2dst = (__half2*)w2h;
#pragma unroll 4
                for (int i = 0; i < 32; i++) {
                    size_t idx = base + (size_t)i * 128;
                    float4 v = __ldg(&w2src[idx]);
                    w2dst[2 * idx]     = __floats2half2_rn(v.x, v.y);
                    w2dst[2 * idx + 1] = __floats2half2_rn(v.z, v.w);
                }
            }
            __threadfence(); __syncthreads();
            if (tid == 0) atomicAdd(&g_cnt_g1[p], 1u);
            continue;
        }

        // ------------------------------------------------------------------
        // GEMM2 tile (p, bm, bn): fused L3 partials (waits g1[p] complete)
        // ------------------------------------------------------------------
        {
            const int r = item - G2BASE;
            const int p = r >> 6;
            const int tl = r & 63;
            const int bn = tl & 7, bm = tl >> 3;
            if (tid == 0) {
                while (ld_acq(&g_cnt_g1[p]) < 128) __nanosleep(64);
            }
            __syncthreads();

            // stage W3 tile
            {
                const float4* w3g = (const float4*)(W3 + ((size_t)p * N2_ + bn * BN) * OUTP);
                ((float4*)(smem_c + W3_OFF))[tid] = __ldg(&w3g[tid]);
            }

            float acc[4][8][4];
#pragma unroll
            for (int mf = 0; mf < 4; mf++)
#pragma unroll
                for (int nf = 0; nf < 8; nf++)
#pragma unroll
                    for (int i = 0; i < 4; i++) acc[mf][nf][i] = 0.f;

            const __half* Wp = w2h + (size_t)p * K2_ * N2_ + (size_t)bn * BN;

            auto load_A = [&](int kt, int buf) {
                uint32_t sbase = smem_u + buf * STGB;
#pragma unroll
                for (int i = 0; i < 8; i++) {
                    int c  = tid + i * 128;
                    int m  = c >> 3;
                    int kl = (c & 7) * 8;
                    const __half* ga = h1h + ((size_t)p * B_ + bm * BM + m) * (size_t)K2_
                                     + kt * BK + kl;
                    cp_async16(sbase + (m * ASTRH + kl) * 2, ga, 16);
                }
            };
            auto load_B = [&](int kt, int buf) {
                uint32_t sbase = smem_u + buf * STGB;
#pragma unroll
                for (int i = 0; i < 8; i++) {
                    int c  = tid + i * 128;
                    int kb = c >> 4;
                    int nb = (c & 15) * 8;
                    const __half* gb = Wp + (size_t)(kt * BK + kb) * N2_ + nb;
                    cp_async16(sbase + ASZB + (kb * BSTRH + nb) * 2, gb, 16);
                }
            };

            uint32_t a[2][4][4], b[2][4][4];
            auto prefetch = [&](uint32_t sbase, int ks, int buf) {
                const uint32_t akk = sbase + aoff + ks * 32;
                const uint32_t bkk = sbase + boff + ks * (16 * BSTRH * 2);
#pragma unroll
                for (int f = 0; f < 4; f++) ldsm4(akk + f * (16 * ASTRH * 2), a[buf][f]);
#pragma unroll
                for (int nf = 0; nf < 4; nf++) ldsm4t(bkk + nf * 32, b[buf][nf]);
            };
            auto mma_block = [&](int buf) {
#pragma unroll
                for (int mf = 0; mf < 4; mf++)
#pragma unroll
                    for (int nf = 0; nf < 4; nf++) {
                        mma_f16_f32(acc[mf][2 * nf],     a[buf][mf], &b[buf][nf][0]);
                        mma_f16_f32(acc[mf][2 * nf + 1], a[buf][mf], &b[buf][nf][2]);
                    }
            };

            const int NKT = K2_ / BK;   // 32

            load_A(0, 0); load_B(0, 0); cp_commit();
            load_A(1, 1); load_B(1, 1); cp_commit();
            cp_wait<1>(); __syncthreads();
            prefetch(smem_u, 0, 0);

            for (int kt = 0; kt < NKT; ++kt) {
                const uint32_t sbase = smem_u + (kt % NSTG) * STGB;
                const bool more = (kt + 2 < NKT);
                const int  nbuf = (kt + 2) % NSTG;

                prefetch(sbase, 1, 1);
                if (more) load_A(kt + 2, nbuf);
                mma_block(0);
                prefetch(sbase, 2, 0);
                if (more) load_B(kt + 2, nbuf);
                mma_block(1);
                prefetch(sbase, 3, 1);
                mma_block(0);

                if (more) { cp_commit(); cp_wait<1>(); }
                else      { cp_wait<0>(); }
                __syncthreads();
                if (kt + 1 < NKT) prefetch(smem_u + ((kt + 1) % NSTG) * STGB, 0, 0);
                mma_block(1);
            }

            // Fused epilogue: h2 = gelu(acc + b2); partials vs W3
            const float* brow = b2 + (size_t)p * N2_;
            const float4* w3s = (const float4*)(smem_c + W3_OFF);
            float* sred = (float*)(smem_c + SRED_OFF);
            float pr[8][4];
#pragma unroll
            for (int rr = 0; rr < 8; rr++)
#pragma unroll
                for (int o = 0; o < 4; o++) pr[rr][o] = 0.f;

#pragma unroll
            for (int mf = 0; mf < 4; mf++) {
#pragma unroll
                for (int nf = 0; nf < 8; nf++) {
                    int ncol = warpN * 64 + nf * 8 + cc * 2;
                    float bv0 = __ldg(brow + bn * BN + ncol);
                    float bv1 = __ldg(brow + bn * BN + ncol + 1);
                    float v0 = gelu_exact(acc[mf][nf][0] + bv0);
                    float v1 = gelu_exact(acc[mf][nf][1] + bv1);
                    float v2 = gelu_exact(acc[mf][nf][2] + bv0);
                    float v3 = gelu_exact(acc[mf][nf][3] + bv1);
                    float4 wA = w3s[ncol];
                    float4 wB = w3s[ncol + 1];
                    int r0 = mf * 2, r1 = mf * 2 + 1;
                    pr[r0][0] += v0 * wA.x + v1 * wB.x;
                    pr[r0][1] += v0 * wA.y + v1 * wB.y;
                    pr[r0][2] += v0 * wA.z + v1 * wB.z;
                    pr[r0][3] += v0 * wA.w + v1 * wB.w;
                    pr[r1][0] += v2 * wA.x + v3 * wB.x;
                    pr[r1][1] += v2 * wA.y + v3 * wB.y;
                    pr[r1][2] += v2 * wA.z + v3 * wB.z;
                    pr[r1][3] += v2 * wA.w + v3 * wB.w;
                }
            }
#pragma unroll
            for (int rr = 0; rr < 8; rr++)
#pragma unroll
                for (int o = 0; o < 4; o++) {
                    float v = pr[rr][o];
                    v += __shfl_xor_sync(0xffffffffu, v, 1);
                    v += __shfl_xor_sync(0xffffffffu, v, 2);
                    pr[rr][o] = v;
                }
            if (cc == 0) {
#pragma unroll
                for (int rr = 0; rr < 8; rr++) {
                    int row = warpM * 64 + (rr >> 1) * 16 + (rr & 1) * 8 + g;
#pragma unroll
                    for (int o = 0; o < 4; o++)
                        sred[row * 8 + o * 2 + warpN] = pr[rr][o];
                }
            }
            __syncthreads();
            {
                int row = tid;
                size_t base = (((size_t)p * B_ + bm * BM + row) * 8 + bn) * OUTP;
#pragma unroll
                for (int o = 0; o < 4; o++)
                    part[base + o] = sred[row * 8 + o * 2] + sred[row * 8 + o * 2 + 1];
            }
            __syncthreads();   // sred reuse safety before next tile's W3 store
        }
    }
}

// ---------------------------------------------------------------------------
// L3 finisher: out[b, p*4+o] = relu(b3[p][o] + sum_{q=0..7} part[p][b][q][o])
// ---------------------------------------------------------------------------
__global__ void l3f_kernel(const float* __restrict__ part, const float* __restrict__ b3,
                           float* __restrict__ out) {
    int idx = blockIdx.x * blockDim.x + threadIdx.x;
    if (idx >= B_ * P_ * OUTP) return;
    int b = idx / (P_ * OUTP);
    int q = idx % (P_ * OUTP);
    int p = q / OUTP;
    int o = q % OUTP;
    const float* pp = part + (((size_t)p * B_ + b) * 8) * OUTP + o;
    float s = b3[p * OUTP + o];
#pragma unroll
    for (int j = 0; j < 8; j++) s += pp[j * OUTP];
    out[idx] = fmaxf(s, 0.f);
}

// ---------------------------------------------------------------------------
extern "C" void kernel_launch(void* const* d_in, const int* in_sizes, int n_in,
                              void* d_out, int out_size) {
    const float* x  = (const float*)d_in[0];
    const float* W1 = (const float*)d_in[1];
    const float* b1 = (const float*)d_in[2];
    const float* W2 = (const float*)d_in[3];
    const float* b2 = (const float*)d_in[4];
    const float* W3 = (const float*)d_in[5];
    const float* b3 = (const float*)d_in[6];
    float* out = (float*)d_out;

    __half *xh, *w1h, *w2h, *h1h;
    float *part;
    cudaGetSymbolAddress((void**)&xh,  g_xh);
    cudaGetSymbolAddress((void**)&w1h, g_w1h);
    cudaGetSymbolAddress((void**)&w2h, g_w2h);
    cudaGetSymbolAddress((void**)&h1h, g_h1h);
    cudaGetSymbolAddress((void**)&part, g_part);

    int smCount = 148;
    cudaDeviceGetAttribute(&smCount, cudaDevAttrMultiProcessorCount, 0);
    const int nCTA = 2 * smCount;

    cudaFuncSetAttribute((const void*)mega_kernel,
                         cudaFuncAttributeMaxDynamicSharedMemorySize, SMEM_ALL);

    // Reset counters (must be first each replay)
    reset_kernel<<<1, 1>>>();
    // Fused: x cvt + W1 cvt + GEMM1(+W2 cvt) + GEMM2(+L3 partials)
    mega_kernel<<<nCTA, 128, SMEM_ALL>>>(x, W1, b1, W2, b2, W3,
                                         xh, w1h, w2h, h1h, part);
    // L3 finisher
    l3f_kernel<<<(B_ * P_ * OUTP + 255) / 256, 256>>>(part, b3, out);
}